// round 6
// baseline (speedup 1.0000x reference)
#include <cuda_runtime.h>
#include <math.h>

#define B_   8
#define N_   1024
#define D_   1024
#define H_   16
#define P_   64
#define DFF_ 4096
#define M_   (B_*N_)          // 8192 tokens
#define FACTOR_ 0.125f        // 1/sqrt(64)

// ---------------- scratch (static device arrays; no allocations) ----------------
__device__ float g_z1[M_*D_];
__device__ float g_q [M_*D_];   // [b][h][n][p]
__device__ float g_k [M_*D_];
__device__ float g_v [M_*D_];
__device__ float g_s1[M_*D_];
__device__ float g_z2[M_*D_];
__device__ float g_h1[33554432]; // 8192 x 4096

// ---------------- layernorm ----------------
// SRC==0: in = x (param), out = g_z1 ; SRC==1: in = g_s1, out = g_z2
template<int SRC>
__global__ void __launch_bounds__(256) ln_kernel(const float* __restrict__ xin,
                                                 const float* __restrict__ gamma,
                                                 const float* __restrict__ beta)
{
    const float* in = (SRC == 0) ? xin : g_s1;
    float* out      = (SRC == 0) ? g_z1 : g_z2;
    int row = blockIdx.x;
    int tid = threadIdx.x;
    const float4* xr = (const float4*)(in + (size_t)row * D_);
    float4 v = xr[tid];
    float s  = v.x + v.y + v.z + v.w;
    float sq = v.x*v.x + v.y*v.y + v.z*v.z + v.w*v.w;
    #pragma unroll
    for (int off = 16; off; off >>= 1) {
        s  += __shfl_xor_sync(0xffffffffu, s,  off);
        sq += __shfl_xor_sync(0xffffffffu, sq, off);
    }
    __shared__ float red0[8], red1[8];
    int w = tid >> 5, l = tid & 31;
    if (l == 0) { red0[w] = s; red1[w] = sq; }
    __syncthreads();
    if (tid < 32) {
        s  = (tid < 8) ? red0[tid] : 0.f;
        sq = (tid < 8) ? red1[tid] : 0.f;
        #pragma unroll
        for (int off = 4; off; off >>= 1) {
            s  += __shfl_xor_sync(0xffffffffu, s,  off);
            sq += __shfl_xor_sync(0xffffffffu, sq, off);
        }
        if (tid == 0) { red0[0] = s; red1[0] = sq; }
    }
    __syncthreads();
    float mu  = red0[0] * (1.0f/1024.0f);
    float var = red1[0] * (1.0f/1024.0f) - mu * mu;
    float rs  = rsqrtf(var + 1e-5f);
    float4 g4 = ((const float4*)gamma)[tid];
    float4 b4 = ((const float4*)beta)[tid];
    float4 o;
    o.x = (v.x - mu) * rs * g4.x + b4.x;
    o.y = (v.y - mu) * rs * g4.y + b4.y;
    o.z = (v.z - mu) * rs * g4.z + b4.z;
    o.w = (v.w - mu) * rs * g4.w + b4.w;
    ((float4*)(out + (size_t)row * D_))[tid] = o;
}

// ---------------- gelu (tanh approx — matches jax.nn.gelu default) ----------------
__device__ __forceinline__ float gelu_f(float x) {
    float u = 0.7978845608028654f * (x + 0.044715f * x * x * x);
    return 0.5f * x * (1.0f + tanhf(u));
}

// ---------------- SGEMM 128x128x8, 256 threads, 8x8/thread, double-buffered ----------
// MODE 0: A=g_z1, C -> scatter to g_q/g_k/g_v (+bqkv)       N=3072 K=1024
// MODE 1: A=g_z2, C -> g_h1 = gelu(.+b1)                    N=4096 K=1024
// MODE 2: A=g_h1, C -> Cout = . + b2 + g_s1                 N=1024 K=4096
template<int MODE>
__global__ void __launch_bounds__(256, 2) sgemm_kernel(const float* __restrict__ Bmat,
                                                       const float* __restrict__ bias,
                                                       float* __restrict__ Cout,
                                                       int N, int K)
{
    const float* A = (MODE == 0) ? g_z1 : (MODE == 1) ? g_z2 : g_h1;
    __shared__ float As[2][8][128];
    __shared__ float Bs[2][8][128];
    int tid = threadIdx.x;
    int bm = blockIdx.y * 128;
    int bn = blockIdx.x * 128;
    int tx = tid & 15, ty = tid >> 4;
    int ar = tid >> 1,  ac = (tid & 1) * 4;
    int br = tid >> 5,  bc = (tid & 31) * 4;
    const float* Ap = A    + (size_t)(bm + ar) * K + ac;
    const float* Bp = Bmat + (size_t)br * N + bn + bc;

    float acc[8][8];
    #pragma unroll
    for (int i = 0; i < 8; i++)
        #pragma unroll
        for (int j = 0; j < 8; j++) acc[i][j] = 0.f;

    // prologue: stage k-tile 0 into buffer 0
    float4 av = *(const float4*)(Ap);
    float4 bv = *(const float4*)(Bp);
    As[0][ac + 0][ar] = av.x; As[0][ac + 1][ar] = av.y;
    As[0][ac + 2][ar] = av.z; As[0][ac + 3][ar] = av.w;
    *(float4*)&Bs[0][br][bc] = bv;
    __syncthreads();

    int buf = 0;
    int ntiles = K >> 3;
    for (int t = 0; t < ntiles; t++) {
        // prefetch next tile into registers (latency hidden under compute below)
        if (t + 1 < ntiles) {
            int kk = (t + 1) << 3;
            av = *(const float4*)(Ap + kk);
            bv = *(const float4*)(Bp + (size_t)kk * N);
        }
        #pragma unroll
        for (int k = 0; k < 8; k++) {
            float a[8], bb[8];
            *(float4*)&a[0]  = *(const float4*)&As[buf][k][ty * 4];
            *(float4*)&a[4]  = *(const float4*)&As[buf][k][64 + ty * 4];
            *(float4*)&bb[0] = *(const float4*)&Bs[buf][k][tx * 4];
            *(float4*)&bb[4] = *(const float4*)&Bs[buf][k][64 + tx * 4];
            #pragma unroll
            for (int i = 0; i < 8; i++)
                #pragma unroll
                for (int j = 0; j < 8; j++)
                    acc[i][j] = fmaf(a[i], bb[j], acc[i][j]);
        }
        if (t + 1 < ntiles) {
            int nb = buf ^ 1;
            As[nb][ac + 0][ar] = av.x; As[nb][ac + 1][ar] = av.y;
            As[nb][ac + 2][ar] = av.z; As[nb][ac + 3][ar] = av.w;
            *(float4*)&Bs[nb][br][bc] = bv;
            __syncthreads();
            buf = nb;
        }
    }

    #pragma unroll
    for (int i = 0; i < 8; i++) {
        int m = bm + ((i < 4) ? (ty * 4 + i) : (64 + ty * 4 + i - 4));
        #pragma unroll
        for (int jj = 0; jj < 2; jj++) {
            int c = bn + (jj ? (64 + tx * 4) : (tx * 4));
            float4 v;
            v.x = acc[i][jj*4+0] + bias[c+0];
            v.y = acc[i][jj*4+1] + bias[c+1];
            v.z = acc[i][jj*4+2] + bias[c+2];
            v.w = acc[i][jj*4+3] + bias[c+3];
            if (MODE == 0) {
                int which = c >> 10;
                int rem = c & 1023;
                int hh = rem >> 6, p = rem & 63;
                int bb2 = m >> 10, tok = m & 1023;
                float* dst = (which == 0) ? g_q : (which == 1) ? g_k : g_v;
                size_t off = ((size_t)(bb2 * H_ + hh) * N_ + tok) * P_ + p;
                *(float4*)&dst[off] = v;
            } else if (MODE == 1) {
                v.x = gelu_f(v.x); v.y = gelu_f(v.y);
                v.z = gelu_f(v.z); v.w = gelu_f(v.w);
                *(float4*)&g_h1[(size_t)m * DFF_ + c] = v;
            } else {
                const float4 r = *(const float4*)&g_s1[(size_t)m * D_ + c];
                v.x += r.x; v.y += r.y; v.z += r.z; v.w += r.w;
                *(float4*)&Cout[(size_t)m * D_ + c] = v;
            }
        }
    }
}

// ---------------- flash attention: 128-query tile per block, 64-wide K/V tiles -------
// grid (128 bh, 8 qtiles), 256 threads; thread = (tr 0..15) x (tc 0..15),
// owns 8 rows (tr*8+i) x 4 cols (tc*4+j). Writes s1 = x + attn_out.
// smem: Qt[64p][132] (Q^T), Kt[64p][68] (K^T), St[64j][132] (P^T), Vs[64j][64p].
#define ATTN_SMEM_BYTES ((64*132 + 64*68 + 64*132 + 64*64) * 4)

__global__ void __launch_bounds__(256) attn_kernel(const float* __restrict__ prior,
                                                   const float* __restrict__ alpha_p,
                                                   const float* __restrict__ x)
{
    extern __shared__ float sm[];
    float* Qt = sm;                          // 64*132
    float* Kt = Qt + 64 * 132;               // 64*68
    float* St = Kt + 64 * 68;                // 64*132
    float* Vs = St + 64 * 132;               // 64*64
    int tid = threadIdx.x;
    int bh = blockIdx.x;
    int b = bh >> 4, h = bh & 15;
    int qt = blockIdx.y;                     // 0..7
    int tr = tid >> 4, tc = tid & 15;
    float alpha = alpha_p[0];

    // stage Q^T once: 128 rows x 64 p
    const float* Qg = g_q + ((size_t)bh * N_ + qt * 128) * P_;
    for (int idx = tid; idx < 128 * 64; idx += 256) {
        int r = idx >> 6, p = idx & 63;
        Qt[p * 132 + r] = Qg[idx];
    }

    float acc[8][4];
    float mrow[8], lrow[8];
    #pragma unroll
    for (int i = 0; i < 8; i++) {
        mrow[i] = -1e30f; lrow[i] = 0.f;
        #pragma unroll
        for (int j = 0; j < 4; j++) acc[i][j] = 0.f;
    }

    int qrow0 = qt * 128 + tr * 8;

    for (int kt = 0; kt < 16; kt++) {
        const float* Kg = g_k + ((size_t)bh * N_ + kt * 64) * P_;
        const float* Vg = g_v + ((size_t)bh * N_ + kt * 64) * P_;
        __syncthreads();   // prior-iter readers of Kt/Vs/St done (also covers Qt staging)
        for (int idx = tid; idx < 64 * 64; idx += 256) {
            int r = idx >> 6, p = idx & 63;
            Kt[p * 68 + r] = Kg[idx];
            Vs[idx]        = Vg[idx];
        }

        // prefetch prior tile for this iteration (latency hidden under QK^T below)
        int kcol0 = kt * 64 + tc * 4;
        float4 pr[8];
        #pragma unroll
        for (int i = 0; i < 8; i++)
            pr[i] = *(const float4*)&prior[((size_t)b * N_ + qrow0 + i) * N_ + kcol0];

        __syncthreads();

        // S = Q K^T (tile 128x64)
        float s[8][4];
        #pragma unroll
        for (int i = 0; i < 8; i++)
            #pragma unroll
            for (int j = 0; j < 4; j++) s[i][j] = 0.f;
        #pragma unroll 4
        for (int p = 0; p < 64; p++) {
            float a[8], bb[4];
            *(float4*)&a[0]  = *(const float4*)&Qt[p * 132 + tr * 8];
            *(float4*)&a[4]  = *(const float4*)&Qt[p * 132 + tr * 8 + 4];
            *(float4*)&bb[0] = *(const float4*)&Kt[p * 68  + tc * 4];
            #pragma unroll
            for (int i = 0; i < 8; i++)
                #pragma unroll
                for (int j = 0; j < 4; j++)
                    s[i][j] = fmaf(a[i], bb[j], s[i][j]);
        }

        // prior + scale + online softmax (rows reduced over the 16 lanes sharing tr)
        #pragma unroll
        for (int i = 0; i < 8; i++) {
            s[i][0] = (s[i][0] + alpha * pr[i].x) * FACTOR_;
            s[i][1] = (s[i][1] + alpha * pr[i].y) * FACTOR_;
            s[i][2] = (s[i][2] + alpha * pr[i].z) * FACTOR_;
            s[i][3] = (s[i][3] + alpha * pr[i].w) * FACTOR_;
            float mx = fmaxf(fmaxf(s[i][0], s[i][1]), fmaxf(s[i][2], s[i][3]));
            #pragma unroll
            for (int off = 1; off < 16; off <<= 1)
                mx = fmaxf(mx, __shfl_xor_sync(0xffffffffu, mx, off));
            float mnew = fmaxf(mrow[i], mx);
            float sc = __expf(mrow[i] - mnew);
            float rsum = 0.f;
            #pragma unroll
            for (int j = 0; j < 4; j++) {
                float wv = __expf(s[i][j] - mnew);
                s[i][j] = wv;
                rsum += wv;
            }
            #pragma unroll
            for (int off = 1; off < 16; off <<= 1)
                rsum += __shfl_xor_sync(0xffffffffu, rsum, off);
            lrow[i] = lrow[i] * sc + rsum;
            mrow[i] = mnew;
            acc[i][0] *= sc; acc[i][1] *= sc; acc[i][2] *= sc; acc[i][3] *= sc;
        }

        // store P^T
        #pragma unroll
        for (int i = 0; i < 8; i++)
            #pragma unroll
            for (int j = 0; j < 4; j++)
                St[(tc * 4 + j) * 132 + tr * 8 + i] = s[i][j];
        __syncthreads();

        // O += P V
        #pragma unroll 4
        for (int j = 0; j < 64; j++) {
            float a[8], vv[4];
            *(float4*)&a[0]  = *(const float4*)&St[j * 132 + tr * 8];
            *(float4*)&a[4]  = *(const float4*)&St[j * 132 + tr * 8 + 4];
            *(float4*)&vv[0] = *(const float4*)&Vs[j * 64 + tc * 4];
            #pragma unroll
            for (int i = 0; i < 8; i++)
                #pragma unroll
                for (int jc = 0; jc < 4; jc++)
                    acc[i][jc] = fmaf(a[i], vv[jc], acc[i][jc]);
        }
    }

    // s1 = x + O/l
    #pragma unroll
    for (int i = 0; i < 8; i++) {
        float inv = 1.0f / lrow[i];
        int qi = qt * 128 + tr * 8 + i;
        size_t off = ((size_t)b * N_ + qi) * D_ + h * P_ + tc * 4;
        float4 xv = *(const float4*)&x[off];
        float4 o;
        o.x = xv.x + acc[i][0] * inv;
        o.y = xv.y + acc[i][1] * inv;
        o.z = xv.z + acc[i][2] * inv;
        o.w = xv.w + acc[i][3] * inv;
        *(float4*)&g_s1[off] = o;
    }
}

// ---------------- launch ----------------
extern "C" void kernel_launch(void* const* d_in, const int* in_sizes, int n_in,
                              void* d_out, int out_size)
{
    const float* x     = (const float*)d_in[0];
    const float* prior = (const float*)d_in[1];
    const float* Wqkv  = (const float*)d_in[2];
    const float* bqkv  = (const float*)d_in[3];
    const float* alpha = (const float*)d_in[4];
    const float* ln1_g = (const float*)d_in[5];
    const float* ln1_b = (const float*)d_in[6];
    const float* ln2_g = (const float*)d_in[7];
    const float* ln2_b = (const float*)d_in[8];
    const float* w1    = (const float*)d_in[9];
    const float* b1    = (const float*)d_in[10];
    const float* w2    = (const float*)d_in[11];
    const float* b2    = (const float*)d_in[12];
    float* out = (float*)d_out;

    cudaFuncSetAttribute(attn_kernel, cudaFuncAttributeMaxDynamicSharedMemorySize,
                         ATTN_SMEM_BYTES);

    // 1. z1 = LN1(x)
    ln_kernel<0><<<M_, 256>>>(x, ln1_g, ln1_b);
    // 2. qkv GEMM + scatter to head layout
    {
        dim3 g(3072 / 128, M_ / 128);
        sgemm_kernel<0><<<g, 256>>>(Wqkv, bqkv, nullptr, 3072, 1024);
    }
    // 3. flash attention + prior + residual -> s1
    {
        dim3 g(B_ * H_, N_ / 128);
        attn_kernel<<<g, 256, ATTN_SMEM_BYTES>>>(prior, alpha, x);
    }
    // 4. z2 = LN2(s1)
    ln_kernel<1><<<M_, 256>>>(x, ln2_g, ln2_b);
    // 5. h1 = gelu(z2 @ w1 + b1)
    {
        dim3 g(DFF_ / 128, M_ / 128);
        sgemm_kernel<1><<<g, 256>>>(w1, b1, nullptr, DFF_, 1024);
    }
    // 6. out = s1 + h1 @ w2 + b2
    {
        dim3 g(D_ / 128, M_ / 128);
        sgemm_kernel<2><<<g, 256>>>(w2, b2, out, D_, DFF_);
    }
}

// round 9
// speedup vs baseline: 1.5622x; 1.5622x over previous
#include <cuda_runtime.h>
#include <cuda_bf16.h>
#include <mma.h>
#include <math.h>
#include <stdint.h>

using namespace nvcuda;

#define B_   8
#define N_   1024
#define D_   1024
#define H_   16
#define P_   64
#define DFF_ 4096
#define M_   (B_*N_)          // 8192 tokens
#define FACTOR_ 0.125f        // 1/sqrt(64)

// ---------------- scratch (static device arrays; no allocations) ----------------
__device__ float g_q [M_*D_];   // [b][h][n][p]
__device__ float g_k [M_*D_];
__device__ float g_v [M_*D_];
__device__ float g_s1[M_*D_];

// bf16 hi/lo split activations (value ~= hi + lo, ~16 mantissa bits)
__device__ __align__(128) __nv_bfloat16 g_z1h[M_*D_];
__device__ __align__(128) __nv_bfloat16 g_z1l[M_*D_];
__device__ __align__(128) __nv_bfloat16 g_z2h[M_*D_];
__device__ __align__(128) __nv_bfloat16 g_z2l[M_*D_];
__device__ __align__(128) __nv_bfloat16 g_h1h[M_*DFF_];
__device__ __align__(128) __nv_bfloat16 g_h1l[M_*DFF_];

// transposed + hi/lo-split bf16 weights: WT[n][k] = W[k][n]
__device__ __align__(128) __nv_bfloat16 g_wqkvT_hi[3072*1024];
__device__ __align__(128) __nv_bfloat16 g_wqkvT_lo[3072*1024];
__device__ __align__(128) __nv_bfloat16 g_w1T_hi [4096*1024];
__device__ __align__(128) __nv_bfloat16 g_w1T_lo [4096*1024];
__device__ __align__(128) __nv_bfloat16 g_w2T_hi [1024*4096];
__device__ __align__(128) __nv_bfloat16 g_w2T_lo [1024*4096];

// ---------------- small helpers ----------------
__device__ __forceinline__ uint32_t smem_u32(const void* p) {
    uint32_t a;
    asm("{ .reg .u64 t; cvta.to.shared.u64 t, %1; cvt.u32.u64 %0, t; }" : "=r"(a) : "l"(p));
    return a;
}
#define CP_ASYNC16(sa, gp) \
    asm volatile("cp.async.cg.shared.global [%0], [%1], 16;" :: "r"(sa), "l"(gp))
#define CP_COMMIT() asm volatile("cp.async.commit_group;" ::: "memory")
#define CP_WAIT1()  asm volatile("cp.async.wait_group 1;" ::: "memory")
#define CP_WAIT0()  asm volatile("cp.async.wait_group 0;" ::: "memory")

__device__ __forceinline__ float gelu_f(float x) {
    float u = 0.7978845608028654f * (x + 0.044715f * x * x * x);
    return 0.5f * x * (1.0f + tanhf(u));
}

// ---------------- layernorm -> bf16 hi/lo split output ----------------
// SRC==0: in = x (param) -> g_z1h/l ; SRC==1: in = g_s1 -> g_z2h/l
template<int SRC>
__global__ void __launch_bounds__(256) ln_kernel(const float* __restrict__ xin,
                                                 const float* __restrict__ gamma,
                                                 const float* __restrict__ beta)
{
    const float* in = (SRC == 0) ? xin : g_s1;
    __nv_bfloat16* outh = (SRC == 0) ? g_z1h : g_z2h;
    __nv_bfloat16* outl = (SRC == 0) ? g_z1l : g_z2l;
    int row = blockIdx.x;
    int tid = threadIdx.x;
    const float4* xr = (const float4*)(in + (size_t)row * D_);
    float4 v = xr[tid];
    float s  = v.x + v.y + v.z + v.w;
    float sq = v.x*v.x + v.y*v.y + v.z*v.z + v.w*v.w;
    #pragma unroll
    for (int off = 16; off; off >>= 1) {
        s  += __shfl_xor_sync(0xffffffffu, s,  off);
        sq += __shfl_xor_sync(0xffffffffu, sq, off);
    }
    __shared__ float red0[8], red1[8];
    int w = tid >> 5, l = tid & 31;
    if (l == 0) { red0[w] = s; red1[w] = sq; }
    __syncthreads();
    if (tid < 32) {
        s  = (tid < 8) ? red0[tid] : 0.f;
        sq = (tid < 8) ? red1[tid] : 0.f;
        #pragma unroll
        for (int off = 4; off; off >>= 1) {
            s  += __shfl_xor_sync(0xffffffffu, s,  off);
            sq += __shfl_xor_sync(0xffffffffu, sq, off);
        }
        if (tid == 0) { red0[0] = s; red1[0] = sq; }
    }
    __syncthreads();
    float mu  = red0[0] * (1.0f/1024.0f);
    float var = red1[0] * (1.0f/1024.0f) - mu * mu;
    float rs  = rsqrtf(var + 1e-5f);
    float4 g4 = ((const float4*)gamma)[tid];
    float4 b4 = ((const float4*)beta)[tid];
    float o[4];
    o[0] = (v.x - mu) * rs * g4.x + b4.x;
    o[1] = (v.y - mu) * rs * g4.y + b4.y;
    o[2] = (v.z - mu) * rs * g4.z + b4.z;
    o[3] = (v.w - mu) * rs * g4.w + b4.w;
    __nv_bfloat16 hh[4], ll[4];
    #pragma unroll
    for (int i = 0; i < 4; i++) {
        hh[i] = __float2bfloat16_rn(o[i]);
        ll[i] = __float2bfloat16_rn(o[i] - __bfloat162float(hh[i]));
    }
    size_t base = (size_t)row * D_ + tid * 4;
    *(__nv_bfloat162*)(outh + base)     = {hh[0], hh[1]};
    *(__nv_bfloat162*)(outh + base + 2) = {hh[2], hh[3]};
    *(__nv_bfloat162*)(outl + base)     = {ll[0], ll[1]};
    *(__nv_bfloat162*)(outl + base + 2) = {ll[2], ll[3]};
}

// ---------------- weight transpose + hi/lo bf16 split: W[K][N] -> WT[n][k] ----------------
template<int WSEL>
__global__ void __launch_bounds__(256) trans_split(const float* __restrict__ W)
{
    constexpr int K = (WSEL == 2) ? 4096 : 1024;
    constexpr int N = (WSEL == 0) ? 3072 : (WSEL == 1) ? 4096 : 1024;
    __nv_bfloat16* oh = (WSEL == 0) ? g_wqkvT_hi : (WSEL == 1) ? g_w1T_hi : g_w2T_hi;
    __nv_bfloat16* ol = (WSEL == 0) ? g_wqkvT_lo : (WSEL == 1) ? g_w1T_lo : g_w2T_lo;
    __shared__ float t[32][33];
    int n0 = blockIdx.x * 32, k0 = blockIdx.y * 32;
    int lx = threadIdx.x & 31, ly = threadIdx.x >> 5;
    #pragma unroll
    for (int rr = 0; rr < 4; rr++)
        t[ly + rr*8][lx] = W[(size_t)(k0 + ly + rr*8) * N + n0 + lx];
    __syncthreads();
    #pragma unroll
    for (int rr = 0; rr < 4; rr++) {
        int n = n0 + ly + rr*8, k = k0 + lx;
        float f = t[lx][ly + rr*8];
        __nv_bfloat16 h = __float2bfloat16_rn(f);
        __nv_bfloat16 l = __float2bfloat16_rn(f - __bfloat162float(h));
        oh[(size_t)n * K + k] = h;
        ol[(size_t)n * K + k] = l;
    }
}

// ---------------- WMMA bf16x3 GEMM: CTA tile 128x128, KC=64, 512 thr (16 warps) --------
// warp (wid>>2, wid&3) computes 32x32 via 2x2 wmma 16x16x16 frags.
// MODE 0: A=z1 pair  K=1024 B=wqkvT  epi: +bqkv, scatter fp32 q/k/v head layout
// MODE 1: A=z2 pair  K=1024 B=w1T    epi: gelu(.+b1) -> h1 bf16 pair
// MODE 2: A=h1 pair  K=4096 B=w2T    epi: . + b2 + g_s1 -> Cout (fp32)
// smem: 2 buffers x [Ah 128x72 | Al | Bh 128x72 | Bl] bf16 = 2 x 73728 B = 147456 B
#define GEMM_SMEM 147456
#define LDT 72

template<int MODE>
__global__ void __launch_bounds__(512) wgemm(const float* __restrict__ bias,
                                             float* __restrict__ Cout)
{
    constexpr int K = (MODE == 2) ? 4096 : 1024;
    constexpr int T = K / 64;
    const __nv_bfloat16* Ah_g = (MODE == 0) ? g_z1h : (MODE == 1) ? g_z2h : g_h1h;
    const __nv_bfloat16* Al_g = (MODE == 0) ? g_z1l : (MODE == 1) ? g_z2l : g_h1l;
    const __nv_bfloat16* Bh_g = (MODE == 0) ? g_wqkvT_hi : (MODE == 1) ? g_w1T_hi : g_w2T_hi;
    const __nv_bfloat16* Bl_g = (MODE == 0) ? g_wqkvT_lo : (MODE == 1) ? g_w1T_lo : g_w2T_lo;

    extern __shared__ __nv_bfloat16 sm[];
    const uint32_t sbase = smem_u32(sm);
    const int tid = threadIdx.x;
    const int wid = tid >> 5, lane = tid & 31;
    const int bn = blockIdx.x * 128;
    const int bm = blockIdx.y * 128;
    const int wm = (wid >> 2) * 32;     // warp m offset in tile
    const int wn = (wid & 3) * 32;      // warp n offset in tile

    wmma::fragment<wmma::accumulator, 16, 16, 16, float> facc[2][2];
    #pragma unroll
    for (int i = 0; i < 2; i++)
        #pragma unroll
        for (int j = 0; j < 2; j++) wmma::fill_fragment(facc[i][j], 0.0f);

    auto stage = [&](int t, int buf) {
        const int kk = t * 64;
        const uint32_t b0 = sbase + (uint32_t)buf * 73728u;
        #pragma unroll
        for (int s = 0; s < 2; s++) {
            int id = tid + s * 512;
            int row = id >> 3, c8 = id & 7;
            uint32_t so = (uint32_t)(row * (LDT*2) + c8 * 16);
            size_t ga = (size_t)(bm + row) * K + kk + c8 * 8;
            size_t gb = (size_t)(bn + row) * K + kk + c8 * 8;
            CP_ASYNC16(b0 +         so, Ah_g + ga);
            CP_ASYNC16(b0 + 18432 + so, Al_g + ga);
            CP_ASYNC16(b0 + 36864 + so, Bh_g + gb);
            CP_ASYNC16(b0 + 55296 + so, Bl_g + gb);
        }
        CP_COMMIT();
    };

    stage(0, 0);
    for (int t = 0; t < T; t++) {
        if (t + 1 < T) { stage(t + 1, (t + 1) & 1); CP_WAIT1(); }
        else           { CP_WAIT0(); }
        __syncthreads();

        const __nv_bfloat16* As_h = sm + (size_t)(t & 1) * 36864;
        const __nv_bfloat16* As_l = As_h + 9216;
        const __nv_bfloat16* Bs_h = As_h + 18432;
        const __nv_bfloat16* Bs_l = As_h + 27648;

        #pragma unroll
        for (int ks = 0; ks < 4; ks++) {
            const int k0 = ks * 16;
            wmma::fragment<wmma::matrix_a, 16, 16, 16, __nv_bfloat16, wmma::row_major> fah[2], fal[2];
            wmma::fragment<wmma::matrix_b, 16, 16, 16, __nv_bfloat16, wmma::col_major> fbh[2], fbl[2];
            #pragma unroll
            for (int i = 0; i < 2; i++) {
                wmma::load_matrix_sync(fah[i], As_h + (wm + i*16) * LDT + k0, LDT);
                wmma::load_matrix_sync(fal[i], As_l + (wm + i*16) * LDT + k0, LDT);
            }
            #pragma unroll
            for (int j = 0; j < 2; j++) {
                wmma::load_matrix_sync(fbh[j], Bs_h + (wn + j*16) * LDT + k0, LDT);
                wmma::load_matrix_sync(fbl[j], Bs_l + (wn + j*16) * LDT + k0, LDT);
            }
            #pragma unroll
            for (int i = 0; i < 2; i++)
                #pragma unroll
                for (int j = 0; j < 2; j++) {
                    wmma::mma_sync(facc[i][j], fah[i], fbh[j], facc[i][j]);
                    wmma::mma_sync(facc[i][j], fal[i], fbh[j], facc[i][j]);
                    wmma::mma_sync(facc[i][j], fah[i], fbl[j], facc[i][j]);
                }
        }
        __syncthreads();
    }

    // ----- epilogue: per-warp 32x32 via smem transpose-free row-major staging -----
    float* tile = (float*)sm + wid * (32 * 36);
    #pragma unroll
    for (int i = 0; i < 2; i++)
        #pragma unroll
        for (int j = 0; j < 2; j++)
            wmma::store_matrix_sync(tile + (i*16) * 36 + j*16, facc[i][j], 36, wmma::mem_row_major);
    __syncwarp();

    const int c = bn + wn + lane;
    const float bv = bias[c];
    if (MODE == 0) {
        const int which = c >> 10, rem = c & 1023;
        const int hh = rem >> 6, p = rem & 63;
        float* dst = (which == 0) ? g_q : (which == 1) ? g_k : g_v;
        #pragma unroll 4
        for (int i = 0; i < 32; i++) {
            int m = bm + wm + i, bb = m >> 10, tok = m & 1023;
            dst[((size_t)(bb*H_ + hh) * N_ + tok) * P_ + p] = tile[i*36 + lane] + bv;
        }
    } else if (MODE == 1) {
        #pragma unroll 4
        for (int i = 0; i < 32; i++) {
            int m = bm + wm + i;
            float v = gelu_f(tile[i*36 + lane] + bv);
            __nv_bfloat16 h = __float2bfloat16_rn(v);
            __nv_bfloat16 l = __float2bfloat16_rn(v - __bfloat162float(h));
            size_t o = (size_t)m * DFF_ + c;
            g_h1h[o] = h;
            g_h1l[o] = l;
        }
    } else {
        #pragma unroll 4
        for (int i = 0; i < 32; i++) {
            int m = bm + wm + i;
            size_t o = (size_t)m * D_ + c;
            Cout[o] = tile[i*36 + lane] + bv + g_s1[o];
        }
    }
}

// ---------------- flash attention (unchanged, passing) ----------------
#define ATTN_SMEM_BYTES ((64*132 + 64*68 + 64*132 + 64*64) * 4)

__global__ void __launch_bounds__(256) attn_kernel(const float* __restrict__ prior,
                                                   const float* __restrict__ alpha_p,
                                                   const float* __restrict__ x)
{
    extern __shared__ float smf[];
    float* Qt = smf;
    float* Kt = Qt + 64 * 132;
    float* St = Kt + 64 * 68;
    float* Vs = St + 64 * 132;
    int tid = threadIdx.x;
    int bh = blockIdx.x;
    int b = bh >> 4, h = bh & 15;
    int qt = blockIdx.y;
    int tr = tid >> 4, tc = tid & 15;
    float alpha = alpha_p[0];

    const float* Qg = g_q + ((size_t)bh * N_ + qt * 128) * P_;
    for (int idx = tid; idx < 128 * 64; idx += 256) {
        int r2 = idx >> 6, p = idx & 63;
        Qt[p * 132 + r2] = Qg[idx];
    }

    float acc[8][4];
    float mrow[8], lrow[8];
    #pragma unroll
    for (int i = 0; i < 8; i++) {
        mrow[i] = -1e30f; lrow[i] = 0.f;
        #pragma unroll
        for (int j = 0; j < 4; j++) acc[i][j] = 0.f;
    }

    int qrow0 = qt * 128 + tr * 8;

    for (int kt = 0; kt < 16; kt++) {
        const float* Kg = g_k + ((size_t)bh * N_ + kt * 64) * P_;
        const float* Vg = g_v + ((size_t)bh * N_ + kt * 64) * P_;
        __syncthreads();
        for (int idx = tid; idx < 64 * 64; idx += 256) {
            int r2 = idx >> 6, p = idx & 63;
            Kt[p * 68 + r2] = Kg[idx];
            Vs[idx]         = Vg[idx];
        }

        int kcol0 = kt * 64 + tc * 4;
        float4 pr[8];
        #pragma unroll
        for (int i = 0; i < 8; i++)
            pr[i] = *(const float4*)&prior[((size_t)b * N_ + qrow0 + i) * N_ + kcol0];

        __syncthreads();

        float s[8][4];
        #pragma unroll
        for (int i = 0; i < 8; i++)
            #pragma unroll
            for (int j = 0; j < 4; j++) s[i][j] = 0.f;
        #pragma unroll 4
        for (int p = 0; p < 64; p++) {
            float a[8], bb[4];
            *(float4*)&a[0]  = *(const float4*)&Qt[p * 132 + tr * 8];
            *(float4*)&a[4]  = *(const float4*)&Qt[p * 132 + tr * 8 + 4];
            *(float4*)&bb[0] = *(const float4*)&Kt[p * 68  + tc * 4];
            #pragma unroll
            for (int i = 0; i < 8; i++)
                #pragma unroll
                for (int j = 0; j < 4; j++)
                    s[i][j] = fmaf(a[i], bb[j], s[i][j]);
        }

        #pragma unroll
        for (int i = 0; i < 8; i++) {
            s[i][0] = (s[i][0] + alpha * pr[i].x) * FACTOR_;
            s[i][1] = (s[i][1] + alpha * pr[i].y) * FACTOR_;
            s[i][2] = (s[i][2] + alpha * pr[i].z) * FACTOR_;
            s[i][3] = (s[i][3] + alpha * pr[i].w) * FACTOR_;
            float mx = fmaxf(fmaxf(s[i][0], s[i][1]), fmaxf(s[i][2], s[i][3]));
            #pragma unroll
            for (int off = 1; off < 16; off <<= 1)
                mx = fmaxf(mx, __shfl_xor_sync(0xffffffffu, mx, off));
            float mnew = fmaxf(mrow[i], mx);
            float sc = __expf(mrow[i] - mnew);
            float rsum = 0.f;
            #pragma unroll
            for (int j = 0; j < 4; j++) {
                float wv = __expf(s[i][j] - mnew);
                s[i][j] = wv;
                rsum += wv;
            }
            #pragma unroll
            for (int off = 1; off < 16; off <<= 1)
                rsum += __shfl_xor_sync(0xffffffffu, rsum, off);
            lrow[i] = lrow[i] * sc + rsum;
            mrow[i] = mnew;
            acc[i][0] *= sc; acc[i][1] *= sc; acc[i][2] *= sc; acc[i][3] *= sc;
        }

        #pragma unroll
        for (int i = 0; i < 8; i++)
            #pragma unroll
            for (int j = 0; j < 4; j++)
                St[(tc * 4 + j) * 132 + tr * 8 + i] = s[i][j];
        __syncthreads();

        #pragma unroll 4
        for (int j = 0; j < 64; j++) {
            float a[8], vv[4];
            *(float4*)&a[0]  = *(const float4*)&St[j * 132 + tr * 8];
            *(float4*)&a[4]  = *(const float4*)&St[j * 132 + tr * 8 + 4];
            *(float4*)&vv[0] = *(const float4*)&Vs[j * 64 + tc * 4];
            #pragma unroll
            for (int i = 0; i < 8; i++)
                #pragma unroll
                for (int jc = 0; jc < 4; jc++)
                    acc[i][jc] = fmaf(a[i], vv[jc], acc[i][jc]);
        }
    }

    #pragma unroll
    for (int i = 0; i < 8; i++) {
        float inv = 1.0f / lrow[i];
        int qi = qt * 128 + tr * 8 + i;
        size_t off = ((size_t)b * N_ + qi) * D_ + h * P_ + tc * 4;
        float4 xv = *(const float4*)&x[off];
        float4 o;
        o.x = xv.x + acc[i][0] * inv;
        o.y = xv.y + acc[i][1] * inv;
        o.z = xv.z + acc[i][2] * inv;
        o.w = xv.w + acc[i][3] * inv;
        *(float4*)&g_s1[off] = o;
    }
}

// ---------------- launch ----------------
extern "C" void kernel_launch(void* const* d_in, const int* in_sizes, int n_in,
                              void* d_out, int out_size)
{
    const float* x     = (const float*)d_in[0];
    const float* prior = (const float*)d_in[1];
    const float* Wqkv  = (const float*)d_in[2];
    const float* bqkv  = (const float*)d_in[3];
    const float* alpha = (const float*)d_in[4];
    const float* ln1_g = (const float*)d_in[5];
    const float* ln1_b = (const float*)d_in[6];
    const float* ln2_g = (const float*)d_in[7];
    const float* ln2_b = (const float*)d_in[8];
    const float* w1    = (const float*)d_in[9];
    const float* b1    = (const float*)d_in[10];
    const float* w2    = (const float*)d_in[11];
    const float* b2    = (const float*)d_in[12];
    float* out = (float*)d_out;

    cudaFuncSetAttribute(attn_kernel, cudaFuncAttributeMaxDynamicSharedMemorySize,
                         ATTN_SMEM_BYTES);
    cudaFuncSetAttribute(wgemm<0>, cudaFuncAttributeMaxDynamicSharedMemorySize, GEMM_SMEM);
    cudaFuncSetAttribute(wgemm<1>, cudaFuncAttributeMaxDynamicSharedMemorySize, GEMM_SMEM);
    cudaFuncSetAttribute(wgemm<2>, cudaFuncAttributeMaxDynamicSharedMemorySize, GEMM_SMEM);

    // 0. weight transpose + bf16 hi/lo split
    trans_split<0><<<dim3(3072/32, 1024/32), 256>>>(Wqkv);
    trans_split<1><<<dim3(4096/32, 1024/32), 256>>>(w1);
    trans_split<2><<<dim3(1024/32, 4096/32), 256>>>(w2);

    // 1. z1 = LN1(x)  (bf16 pair)
    ln_kernel<0><<<M_, 256>>>(x, ln1_g, ln1_b);
    // 2. qkv = z1 @ Wqkv + bqkv  (wmma bf16x3) -> fp32 q/k/v head layout
    wgemm<0><<<dim3(3072/128, M_/128), 512, GEMM_SMEM>>>(bqkv, nullptr);
    // 3. flash attention + prior + residual -> s1 (fp32)
    attn_kernel<<<dim3(B_*H_, N_/128), 256, ATTN_SMEM_BYTES>>>(prior, alpha, x);
    // 4. z2 = LN2(s1)  (bf16 pair)
    ln_kernel<1><<<M_, 256>>>(x, ln2_g, ln2_b);
    // 5. h1 = gelu(z2 @ w1 + b1)  (bf16 pair)
    wgemm<1><<<dim3(4096/128, M_/128), 512, GEMM_SMEM>>>(b1, nullptr);
    // 6. out = s1 + h1 @ w2 + b2  (fp32)
    wgemm<2><<<dim3(1024/128, M_/128), 512, GEMM_SMEM>>>(b2, out);
}

// round 12
// speedup vs baseline: 2.4617x; 1.5758x over previous
#include <cuda_runtime.h>
#include <cuda_fp16.h>
#include <mma.h>
#include <math.h>
#include <stdint.h>

using namespace nvcuda;

#define B_   8
#define N_   1024
#define D_   1024
#define H_   16
#define P_   64
#define DFF_ 4096
#define M_   (B_*N_)          // 8192 tokens
#define FACTOR_ 0.125f        // 1/sqrt(64)

// ---------------- scratch (static device arrays; no allocations) ----------------
__device__ float g_s1[M_*D_];

// fp16 q/k/v in head layout [bh][n][p]
__device__ __align__(128) __half g_qh[M_*D_];
__device__ __align__(128) __half g_kh[M_*D_];
__device__ __align__(128) __half g_vh[M_*D_];

// fp16 hi/lo split activations (value ~= hi + lo, ~22 mantissa bits)
__device__ __align__(128) __half g_z1h[M_*D_];
__device__ __align__(128) __half g_z1l[M_*D_];
__device__ __align__(128) __half g_z2h[M_*D_];
__device__ __align__(128) __half g_z2l[M_*D_];
__device__ __align__(128) __half g_h1h[M_*DFF_];
__device__ __align__(128) __half g_h1l[M_*DFF_];

// transposed single-fp16 weights: WT[n][k] = W[k][n]
__device__ __align__(128) __half g_wqkvT[3072*1024];
__device__ __align__(128) __half g_w1T [4096*1024];
__device__ __align__(128) __half g_w2T [1024*4096];

// ---------------- helpers ----------------
__device__ __forceinline__ uint32_t smem_u32(const void* p) {
    uint32_t a;
    asm("{ .reg .u64 t; cvta.to.shared.u64 t, %1; cvt.u32.u64 %0, t; }" : "=r"(a) : "l"(p));
    return a;
}
#define CP_ASYNC16(sa, gp) \
    asm volatile("cp.async.cg.shared.global [%0], [%1], 16;" :: "r"(sa), "l"(gp))
#define CP_COMMIT() asm volatile("cp.async.commit_group;" ::: "memory")
#define CP_WAIT1()  asm volatile("cp.async.wait_group 1;" ::: "memory")
#define CP_WAIT0()  asm volatile("cp.async.wait_group 0;" ::: "memory")

__device__ __forceinline__ float gelu_f(float x) {
    float u = 0.7978845608028654f * (x + 0.044715f * x * x * x);
    return 0.5f * x * (1.0f + tanhf(u));
}

// ---------------- layernorm -> fp16 hi/lo split output ----------------
template<int SRC>
__global__ void __launch_bounds__(256) ln_kernel(const float* __restrict__ xin,
                                                 const float* __restrict__ gamma,
                                                 const float* __restrict__ beta)
{
    const float* in = (SRC == 0) ? xin : g_s1;
    __half* outh = (SRC == 0) ? g_z1h : g_z2h;
    __half* outl = (SRC == 0) ? g_z1l : g_z2l;
    int row = blockIdx.x;
    int tid = threadIdx.x;
    const float4* xr = (const float4*)(in + (size_t)row * D_);
    float4 v = xr[tid];
    float s  = v.x + v.y + v.z + v.w;
    float sq = v.x*v.x + v.y*v.y + v.z*v.z + v.w*v.w;
    #pragma unroll
    for (int off = 16; off; off >>= 1) {
        s  += __shfl_xor_sync(0xffffffffu, s,  off);
        sq += __shfl_xor_sync(0xffffffffu, sq, off);
    }
    __shared__ float red0[8], red1[8];
    int w = tid >> 5, l = tid & 31;
    if (l == 0) { red0[w] = s; red1[w] = sq; }
    __syncthreads();
    if (tid < 32) {
        s  = (tid < 8) ? red0[tid] : 0.f;
        sq = (tid < 8) ? red1[tid] : 0.f;
        #pragma unroll
        for (int off = 4; off; off >>= 1) {
            s  += __shfl_xor_sync(0xffffffffu, s,  off);
            sq += __shfl_xor_sync(0xffffffffu, sq, off);
        }
        if (tid == 0) { red0[0] = s; red1[0] = sq; }
    }
    __syncthreads();
    float mu  = red0[0] * (1.0f/1024.0f);
    float var = red1[0] * (1.0f/1024.0f) - mu * mu;
    float rs  = rsqrtf(var + 1e-5f);
    float4 g4 = ((const float4*)gamma)[tid];
    float4 b4 = ((const float4*)beta)[tid];
    float o[4];
    o[0] = (v.x - mu) * rs * g4.x + b4.x;
    o[1] = (v.y - mu) * rs * g4.y + b4.y;
    o[2] = (v.z - mu) * rs * g4.z + b4.z;
    o[3] = (v.w - mu) * rs * g4.w + b4.w;
    __half hh[4], ll[4];
    #pragma unroll
    for (int i = 0; i < 4; i++) {
        hh[i] = __float2half_rn(o[i]);
        ll[i] = __float2half_rn(o[i] - __half2float(hh[i]));
    }
    size_t base = (size_t)row * D_ + tid * 4;
    *(__half2*)(outh + base)     = {hh[0], hh[1]};
    *(__half2*)(outh + base + 2) = {hh[2], hh[3]};
    *(__half2*)(outl + base)     = {ll[0], ll[1]};
    *(__half2*)(outl + base + 2) = {ll[2], ll[3]};
}

// ---------------- weight transpose to single fp16: W[K][N] -> WT[n][k] ----------------
template<int WSEL>
__global__ void __launch_bounds__(256) trans_split(const float* __restrict__ W)
{
    constexpr int K = (WSEL == 2) ? 4096 : 1024;
    constexpr int N = (WSEL == 0) ? 3072 : (WSEL == 1) ? 4096 : 1024;
    __half* oh = (WSEL == 0) ? g_wqkvT : (WSEL == 1) ? g_w1T : g_w2T;
    __shared__ float t[32][33];
    int n0 = blockIdx.x * 32, k0 = blockIdx.y * 32;
    int lx = threadIdx.x & 31, ly = threadIdx.x >> 5;
    #pragma unroll
    for (int rr = 0; rr < 4; rr++)
        t[ly + rr*8][lx] = W[(size_t)(k0 + ly + rr*8) * N + n0 + lx];
    __syncthreads();
    #pragma unroll
    for (int rr = 0; rr < 4; rr++) {
        int n = n0 + ly + rr*8, k = k0 + lx;
        oh[(size_t)n * K + k] = __float2half_rn(t[lx][ly + rr*8]);
    }
}

// ---------------- WMMA fp16x2 GEMM: CTA 128x128, KC=64, 3-stage cp.async, 512 thr ------
// C = (Ah + Al) * B   (A 2-term fp16 split, B single fp16; err ~ a*b_lo ~ 2^-12)
// MODE 0: A=z1 pair K=1024 B=wqkvT  epi: +bqkv -> fp16 q/k/v head layout
// MODE 1: A=z2 pair K=1024 B=w1T    epi: gelu(.+b1) -> h1 fp16 pair
// MODE 2: A=h1 pair K=4096 B=w2T    epi: . + b2 + g_s1 -> Cout fp32
// smem/stage: Ah[128x72] Al Bh  = 3*18432B = 55296B; 3 stages = 165888B
#define GEMM_SMEM 165888
#define LDT 72

template<int MODE>
__global__ void __launch_bounds__(512) wgemm(const float* __restrict__ bias,
                                             float* __restrict__ Cout)
{
    constexpr int K = (MODE == 2) ? 4096 : 1024;
    constexpr int T = K / 64;
    const __half* Ah_g = (MODE == 0) ? g_z1h : (MODE == 1) ? g_z2h : g_h1h;
    const __half* Al_g = (MODE == 0) ? g_z1l : (MODE == 1) ? g_z2l : g_h1l;
    const __half* B_g  = (MODE == 0) ? g_wqkvT : (MODE == 1) ? g_w1T : g_w2T;

    extern __shared__ __half sm[];
    const uint32_t sbase = smem_u32(sm);
    const int tid = threadIdx.x;
    const int wid = tid >> 5, lane = tid & 31;
    const int bn = blockIdx.x * 128;
    const int bm = blockIdx.y * 128;
    const int wm = (wid >> 2) * 32;
    const int wn = (wid & 3) * 32;

    wmma::fragment<wmma::accumulator, 16, 16, 16, float> facc[2][2];
    #pragma unroll
    for (int i = 0; i < 2; i++)
        #pragma unroll
        for (int j = 0; j < 2; j++) wmma::fill_fragment(facc[i][j], 0.0f);

    auto stage = [&](int t, int buf) {
        const int kk = t * 64;
        const uint32_t b0 = sbase + (uint32_t)buf * 55296u;
        #pragma unroll
        for (int s = 0; s < 2; s++) {
            int id = tid + s * 512;          // 1024 ids per array
            int row = id >> 3, c8 = id & 7;
            uint32_t so = (uint32_t)(row * 144 + c8 * 16);
            size_t ga = (size_t)(bm + row) * K + kk + c8 * 8;
            size_t gb = (size_t)(bn + row) * K + kk + c8 * 8;
            CP_ASYNC16(b0 +         so, Ah_g + ga);
            CP_ASYNC16(b0 + 18432 + so, Al_g + ga);
            CP_ASYNC16(b0 + 36864 + so, B_g  + gb);
        }
        CP_COMMIT();
    };

    stage(0, 0);
    if (T > 1) stage(1, 1);
    for (int t = 0; t < T; t++) {
        if (t == T - 1) { CP_WAIT0(); } else { CP_WAIT1(); }
        __syncthreads();
        if (t + 2 < T) stage(t + 2, (t + 2) % 3);

        const __half* As_h = sm + (size_t)(t % 3) * 27648;  // 55296B / 2
        const __half* As_l = As_h + 9216;
        const __half* Bs   = As_h + 18432;

        #pragma unroll
        for (int ks = 0; ks < 4; ks++) {
            const int k0 = ks * 16;
            wmma::fragment<wmma::matrix_a, 16, 16, 16, __half, wmma::row_major> fah[2], fal[2];
            wmma::fragment<wmma::matrix_b, 16, 16, 16, __half, wmma::col_major> fb[2];
            #pragma unroll
            for (int i = 0; i < 2; i++) {
                wmma::load_matrix_sync(fah[i], As_h + (wm + i*16) * LDT + k0, LDT);
                wmma::load_matrix_sync(fal[i], As_l + (wm + i*16) * LDT + k0, LDT);
            }
            #pragma unroll
            for (int j = 0; j < 2; j++)
                wmma::load_matrix_sync(fb[j], Bs + (wn + j*16) * LDT + k0, LDT);
            #pragma unroll
            for (int i = 0; i < 2; i++)
                #pragma unroll
                for (int j = 0; j < 2; j++) {
                    wmma::mma_sync(facc[i][j], fah[i], fb[j], facc[i][j]);
                    wmma::mma_sync(facc[i][j], fal[i], fb[j], facc[i][j]);
                }
        }
        __syncthreads();
    }

    // ----- epilogue -----
    float* tile = (float*)sm + wid * (32 * 36);
    #pragma unroll
    for (int i = 0; i < 2; i++)
        #pragma unroll
        for (int j = 0; j < 2; j++)
            wmma::store_matrix_sync(tile + (i*16) * 36 + j*16, facc[i][j], 36, wmma::mem_row_major);
    __syncwarp();

    const int c = bn + wn + lane;
    const float bv = bias[c];
    if (MODE == 0) {
        const int which = c >> 10, rem = c & 1023;
        const int hh = rem >> 6, p = rem & 63;
        __half* dst = (which == 0) ? g_qh : (which == 1) ? g_kh : g_vh;
        #pragma unroll 4
        for (int i = 0; i < 32; i++) {
            int m = bm + wm + i, bb = m >> 10, tok = m & 1023;
            dst[((size_t)(bb*H_ + hh) * N_ + tok) * P_ + p] = __float2half_rn(tile[i*36 + lane] + bv);
        }
    } else if (MODE == 1) {
        #pragma unroll 4
        for (int i = 0; i < 32; i++) {
            int m = bm + wm + i;
            float v = gelu_f(tile[i*36 + lane] + bv);
            __half h = __float2half_rn(v);
            __half l = __float2half_rn(v - __half2float(h));
            size_t o = (size_t)m * DFF_ + c;
            g_h1h[o] = h;
            g_h1l[o] = l;
        }
    } else {
        #pragma unroll 4
        for (int i = 0; i < 32; i++) {
            int m = bm + wm + i;
            size_t o = (size_t)m * D_ + c;
            Cout[o] = tile[i*36 + lane] + bv + g_s1[o];
        }
    }
}

// ---------------- WMMA flash attention: 128-q tile, 64-key tiles, 256 thr (8 warps) ----
// Warp w owns q-rows [w*16, w*16+16). S/O round-trip smem (defined layouts);
// softmax + online rescale in SIMT fp32. Writes s1 = x + O/l.
#define AT_LD 72
#define ATTN_SMEM 130048

__global__ void __launch_bounds__(256) attn_kernel(const float* __restrict__ prior,
                                                   const float* __restrict__ alpha_p,
                                                   const float* __restrict__ x)
{
    extern __shared__ char smc[];
    __half* Qs = (__half*)smc;                   // 128 x 72 fp16
    __half* Ks = (__half*)(smc + 18432);         // 64  x 72 fp16 (row j, cols p)
    __half* Vt = (__half*)(smc + 27648);         // 64  x 72 fp16 (row p, cols j)
    float*  Ss = (float*) (smc + 36864);         // 128 x 72 fp32
    __half* Ps = (__half*)(smc + 73728);         // 128 x 72 fp16
    float*  Os = (float*) (smc + 92160);         // 128 x 72 fp32
    float*  mrow = (float*)(smc + 129024);       // 128
    float*  lrow = (float*)(smc + 129536);       // 128

    const int tid = threadIdx.x;
    const int wid = tid >> 5;
    const int bh = blockIdx.x, b = bh >> 4, h = bh & 15;
    const int qt = blockIdx.y;
    const float alpha = alpha_p[0];

    // stage Q (128 x 64 fp16)
    const __half* Qg = g_qh + ((size_t)bh * N_ + qt * 128) * P_;
    for (int i = tid; i < 1024; i += 256) {
        int r = i >> 3, c8 = i & 7;
        *(uint4*)(Qs + r * AT_LD + c8 * 8) = *(const uint4*)(Qg + r * 64 + c8 * 8);
    }
    for (int i = tid; i < 128; i += 256) { mrow[i] = -1e30f; lrow[i] = 0.f; }
    for (int i = tid; i < 8192; i += 256) {
        int r = i >> 6, c = i & 63;
        Os[r * AT_LD + c] = 0.f;
    }

    const int r_s = tid >> 1, c0 = (tid & 1) * 32;
    const int qrow = qt * 128 + r_s;
    const float* prow = prior + ((size_t)b * N_ + qrow) * N_;

    for (int kt = 0; kt < 16; kt++) {
        __syncthreads();   // prev PV done with Ks/Vt (kt=0: Q/O init done)
        const __half* Kg = g_kh + ((size_t)bh * N_ + kt * 64) * P_;
        const __half* Vg = g_vh + ((size_t)bh * N_ + kt * 64) * P_;
        for (int i = tid; i < 512; i += 256) {
            int r = i >> 3, c8 = i & 7;
            *(uint4*)(Ks + r * AT_LD + c8 * 8) = *(const uint4*)(Kg + r * 64 + c8 * 8);
        }
        for (int i = tid; i < 4096; i += 256) {
            int j = i >> 6, p = i & 63;
            Vt[p * AT_LD + j] = Vg[j * 64 + p];
        }
        // prefetch prior for my (row, 32-col) slice (covered by K/V staging + S mma)
        float4 pr[8];
        #pragma unroll
        for (int i = 0; i < 8; i++)
            pr[i] = *(const float4*)(prow + kt * 64 + c0 + i * 4);
        __syncthreads();

        // ---- S = Q K^T (warp: 16 x 64) ----
        {
            wmma::fragment<wmma::accumulator, 16, 16, 16, float> sacc[4];
            #pragma unroll
            for (int nf = 0; nf < 4; nf++) wmma::fill_fragment(sacc[nf], 0.0f);
            #pragma unroll
            for (int ks = 0; ks < 4; ks++) {
                wmma::fragment<wmma::matrix_a, 16, 16, 16, __half, wmma::row_major> fa;
                wmma::load_matrix_sync(fa, Qs + (wid * 16) * AT_LD + ks * 16, AT_LD);
                #pragma unroll
                for (int nf = 0; nf < 4; nf++) {
                    wmma::fragment<wmma::matrix_b, 16, 16, 16, __half, wmma::col_major> fb;
                    wmma::load_matrix_sync(fb, Ks + (nf * 16) * AT_LD + ks * 16, AT_LD);
                    wmma::mma_sync(sacc[nf], fa, fb, sacc[nf]);
                }
            }
            #pragma unroll
            for (int nf = 0; nf < 4; nf++)
                wmma::store_matrix_sync(Ss + (wid * 16) * AT_LD + nf * 16, sacc[nf],
                                        AT_LD, wmma::mem_row_major);
        }
        __syncthreads();

        // ---- softmax (thread: row r_s, cols c0..c0+31; pair-reduce via shfl xor 1) ----
        {
            float sv[32];
            float mx = -1e30f;
            #pragma unroll
            for (int i = 0; i < 32; i++) {
                float v = Ss[r_s * AT_LD + c0 + i];
                float pv = (&pr[i >> 2].x)[i & 3];
                v = (v + alpha * pv) * FACTOR_;
                sv[i] = v;
                mx = fmaxf(mx, v);
            }
            mx = fmaxf(mx, __shfl_xor_sync(0xffffffffu, mx, 1));
            float mold = mrow[r_s];
            float mnew = fmaxf(mold, mx);
            float rsum = 0.f;
            #pragma unroll
            for (int i = 0; i < 16; i++) {
                float e0 = __expf(sv[2*i]   - mnew);
                float e1 = __expf(sv[2*i+1] - mnew);
                rsum += e0 + e1;
                *(__half2*)(Ps + r_s * AT_LD + c0 + 2*i) =
                    __floats2half2_rn(e0, e1);
            }
            rsum += __shfl_xor_sync(0xffffffffu, rsum, 1);
            float sc = __expf(mold - mnew);
            if ((tid & 1) == 0) { mrow[r_s] = mnew; lrow[r_s] = lrow[r_s] * sc + rsum; }
            #pragma unroll
            for (int i = 0; i < 32; i++)
                Os[r_s * AT_LD + c0 + i] *= sc;
        }
        __syncthreads();

        // ---- O += P V (warp: 16 x 64, acc in smem fp32) ----
        {
            wmma::fragment<wmma::accumulator, 16, 16, 16, float> oacc[4];
            #pragma unroll
            for (int nf = 0; nf < 4; nf++)
                wmma::load_matrix_sync(oacc[nf], Os + (wid * 16) * AT_LD + nf * 16,
                                       AT_LD, wmma::mem_row_major);
            #pragma unroll
            for (int ks = 0; ks < 4; ks++) {
                wmma::fragment<wmma::matrix_a, 16, 16, 16, __half, wmma::row_major> fa;
                wmma::load_matrix_sync(fa, Ps + (wid * 16) * AT_LD + ks * 16, AT_LD);
                #pragma unroll
                for (int nf = 0; nf < 4; nf++) {
                    wmma::fragment<wmma::matrix_b, 16, 16, 16, __half, wmma::col_major> fb;
                    wmma::load_matrix_sync(fb, Vt + (nf * 16) * AT_LD + ks * 16, AT_LD);
                    wmma::mma_sync(oacc[nf], fa, fb, oacc[nf]);
                }
            }
            #pragma unroll
            for (int nf = 0; nf < 4; nf++)
                wmma::store_matrix_sync(Os + (wid * 16) * AT_LD + nf * 16, oacc[nf],
                                        AT_LD, wmma::mem_row_major);
        }
    }
    __syncthreads();

    // ---- s1 = x + O/l ----
    {
        float inv = 1.0f / lrow[r_s];
        size_t off = ((size_t)b * N_ + qrow) * D_ + h * P_ + c0;
        #pragma unroll
        for (int i = 0; i < 8; i++) {
            float4 xv = *(const float4*)(x + off + i * 4);
            float4 o;
            o.x = xv.x + Os[r_s * AT_LD + c0 + i*4 + 0] * inv;
            o.y = xv.y + Os[r_s * AT_LD + c0 + i*4 + 1] * inv;
            o.z = xv.z + Os[r_s * AT_LD + c0 + i*4 + 2] * inv;
            o.w = xv.w + Os[r_s * AT_LD + c0 + i*4 + 3] * inv;
            *(float4*)&g_s1[off + i * 4] = o;
        }
    }
}

// ---------------- launch ----------------
extern "C" void kernel_launch(void* const* d_in, const int* in_sizes, int n_in,
                              void* d_out, int out_size)
{
    const float* x     = (const float*)d_in[0];
    const float* prior = (const float*)d_in[1];
    const float* Wqkv  = (const float*)d_in[2];
    const float* bqkv  = (const float*)d_in[3];
    const float* alpha = (const float*)d_in[4];
    const float* ln1_g = (const float*)d_in[5];
    const float* ln1_b = (const float*)d_in[6];
    const float* ln2_g = (const float*)d_in[7];
    const float* ln2_b = (const float*)d_in[8];
    const float* w1    = (const float*)d_in[9];
    const float* b1    = (const float*)d_in[10];
    const float* w2    = (const float*)d_in[11];
    const float* b2    = (const float*)d_in[12];
    float* out = (float*)d_out;

    cudaFuncSetAttribute(attn_kernel, cudaFuncAttributeMaxDynamicSharedMemorySize, ATTN_SMEM);
    cudaFuncSetAttribute(wgemm<0>, cudaFuncAttributeMaxDynamicSharedMemorySize, GEMM_SMEM);
    cudaFuncSetAttribute(wgemm<1>, cudaFuncAttributeMaxDynamicSharedMemorySize, GEMM_SMEM);
    cudaFuncSetAttribute(wgemm<2>, cudaFuncAttributeMaxDynamicSharedMemorySize, GEMM_SMEM);

    // 0. weight transpose -> fp16
    trans_split<0><<<dim3(3072/32, 1024/32), 256>>>(Wqkv);
    trans_split<1><<<dim3(4096/32, 1024/32), 256>>>(w1);
    trans_split<2><<<dim3(1024/32, 4096/32), 256>>>(w2);

    // 1. z1 = LN1(x)  (fp16 pair)
    ln_kernel<0><<<M_, 256>>>(x, ln1_g, ln1_b);
    // 2. qkv GEMM -> fp16 q/k/v head layout
    wgemm<0><<<dim3(3072/128, M_/128), 512, GEMM_SMEM>>>(bqkv, nullptr);
    // 3. WMMA flash attention + prior + residual -> s1 (fp32)
    attn_kernel<<<dim3(B_*H_, N_/128), 256, ATTN_SMEM>>>(prior, alpha, x);
    // 4. z2 = LN2(s1)  (fp16 pair)
    ln_kernel<1><<<M_, 256>>>(x, ln2_g, ln2_b);
    // 5. h1 = gelu(z2 @ w1 + b1)  (fp16 pair)
    wgemm<1><<<dim3(4096/128, M_/128), 512, GEMM_SMEM>>>(b1, nullptr);
    // 6. out = s1 + h1 @ w2 + b2  (fp32)
    wgemm<2><<<dim3(1024/128, M_/128), 512, GEMM_SMEM>>>(b2, out);
}

// round 13
// speedup vs baseline: 3.6969x; 1.5018x over previous
#include <cuda_runtime.h>
#include <cuda_fp16.h>
#include <mma.h>
#include <math.h>
#include <stdint.h>

using namespace nvcuda;

#define B_   8
#define N_   1024
#define D_   1024
#define H_   16
#define P_   64
#define DFF_ 4096
#define M_   (B_*N_)          // 8192 tokens
#define FACTOR_ 0.125f        // 1/sqrt(64)

// ---------------- scratch (static device arrays; no allocations) ----------------
__device__ float g_s1[M_*D_];

// fp16 q/k/v in head layout [bh][n][p]
__device__ __align__(128) __half g_qh[M_*D_];
__device__ __align__(128) __half g_kh[M_*D_];
__device__ __align__(128) __half g_vh[M_*D_];

// single-fp16 activations
__device__ __align__(128) __half g_z1[M_*D_];
__device__ __align__(128) __half g_z2[M_*D_];
__device__ __align__(128) __half g_h1[M_*DFF_];

// transposed single-fp16 weights: WT[n][k] = W[k][n]
__device__ __align__(128) __half g_wqkvT[3072*1024];
__device__ __align__(128) __half g_w1T [4096*1024];
__device__ __align__(128) __half g_w2T [1024*4096];

// ---------------- helpers ----------------
__device__ __forceinline__ uint32_t smem_u32(const void* p) {
    uint32_t a;
    asm("{ .reg .u64 t; cvta.to.shared.u64 t, %1; cvt.u32.u64 %0, t; }" : "=r"(a) : "l"(p));
    return a;
}
#define CP_ASYNC16(sa, gp) \
    asm volatile("cp.async.cg.shared.global [%0], [%1], 16;" :: "r"(sa), "l"(gp))
#define CP_COMMIT() asm volatile("cp.async.commit_group;" ::: "memory")
#define CP_WAIT1()  asm volatile("cp.async.wait_group 1;" ::: "memory")
#define CP_WAIT0()  asm volatile("cp.async.wait_group 0;" ::: "memory")

__device__ __forceinline__ float gelu_f(float x) {
    float u = 0.7978845608028654f * (x + 0.044715f * x * x * x);
    return 0.5f * x * (1.0f + tanhf(u));
}

// ---------------- layernorm -> single fp16 ----------------
template<int SRC>
__global__ void __launch_bounds__(256) ln_kernel(const float* __restrict__ xin,
                                                 const float* __restrict__ gamma,
                                                 const float* __restrict__ beta)
{
    const float* in = (SRC == 0) ? xin : g_s1;
    __half* outh = (SRC == 0) ? g_z1 : g_z2;
    int row = blockIdx.x;
    int tid = threadIdx.x;
    const float4* xr = (const float4*)(in + (size_t)row * D_);
    float4 v = xr[tid];
    float s  = v.x + v.y + v.z + v.w;
    float sq = v.x*v.x + v.y*v.y + v.z*v.z + v.w*v.w;
    #pragma unroll
    for (int off = 16; off; off >>= 1) {
        s  += __shfl_xor_sync(0xffffffffu, s,  off);
        sq += __shfl_xor_sync(0xffffffffu, sq, off);
    }
    __shared__ float red0[8], red1[8];
    int w = tid >> 5, l = tid & 31;
    if (l == 0) { red0[w] = s; red1[w] = sq; }
    __syncthreads();
    if (tid < 32) {
        s  = (tid < 8) ? red0[tid] : 0.f;
        sq = (tid < 8) ? red1[tid] : 0.f;
        #pragma unroll
        for (int off = 4; off; off >>= 1) {
            s  += __shfl_xor_sync(0xffffffffu, s,  off);
            sq += __shfl_xor_sync(0xffffffffu, sq, off);
        }
        if (tid == 0) { red0[0] = s; red1[0] = sq; }
    }
    __syncthreads();
    float mu  = red0[0] * (1.0f/1024.0f);
    float var = red1[0] * (1.0f/1024.0f) - mu * mu;
    float rs  = rsqrtf(var + 1e-5f);
    float4 g4 = ((const float4*)gamma)[tid];
    float4 b4 = ((const float4*)beta)[tid];
    float o[4];
    o[0] = (v.x - mu) * rs * g4.x + b4.x;
    o[1] = (v.y - mu) * rs * g4.y + b4.y;
    o[2] = (v.z - mu) * rs * g4.z + b4.z;
    o[3] = (v.w - mu) * rs * g4.w + b4.w;
    size_t base = (size_t)row * D_ + tid * 4;
    *(__half2*)(outh + base)     = __floats2half2_rn(o[0], o[1]);
    *(__half2*)(outh + base + 2) = __floats2half2_rn(o[2], o[3]);
}

// ---------------- weight transpose to single fp16: W[K][N] -> WT[n][k] ----------------
template<int WSEL>
__global__ void __launch_bounds__(256) trans_split(const float* __restrict__ W)
{
    constexpr int K = (WSEL == 2) ? 4096 : 1024;
    constexpr int N = (WSEL == 0) ? 3072 : (WSEL == 1) ? 4096 : 1024;
    __half* oh = (WSEL == 0) ? g_wqkvT : (WSEL == 1) ? g_w1T : g_w2T;
    __shared__ float t[32][33];
    int n0 = blockIdx.x * 32, k0 = blockIdx.y * 32;
    int lx = threadIdx.x & 31, ly = threadIdx.x >> 5;
    #pragma unroll
    for (int rr = 0; rr < 4; rr++)
        t[ly + rr*8][lx] = W[(size_t)(k0 + ly + rr*8) * N + n0 + lx];
    __syncthreads();
    #pragma unroll
    for (int rr = 0; rr < 4; rr++) {
        int n = n0 + ly + rr*8, k = k0 + lx;
        oh[(size_t)n * K + k] = __float2half_rn(t[lx][ly + rr*8]);
    }
}

// ---------------- WMMA fp16 GEMM: CTA 128x128, KC=64, 3-stage cp.async, 512 thr --------
// C = A * B  (single fp16 both sides, fp32 accumulate)
// MODE 0: A=z1 K=1024 B=wqkvT  epi: +bqkv -> fp16 q/k/v head layout
// MODE 1: A=z2 K=1024 B=w1T    epi: gelu(.+b1) -> h1 fp16
// MODE 2: A=h1 K=4096 B=w2T    epi: . + b2 + g_s1 -> Cout fp32
// smem/stage: A[128x72] + B[128x72] fp16 = 36864B; 3 stages = 110592B
#define GEMM_SMEM 110592
#define LDT 72

template<int MODE>
__global__ void __launch_bounds__(512) wgemm(const float* __restrict__ bias,
                                             float* __restrict__ Cout)
{
    constexpr int K = (MODE == 2) ? 4096 : 1024;
    constexpr int T = K / 64;
    const __half* A_g = (MODE == 0) ? g_z1 : (MODE == 1) ? g_z2 : g_h1;
    const __half* B_g = (MODE == 0) ? g_wqkvT : (MODE == 1) ? g_w1T : g_w2T;

    extern __shared__ __half sm[];
    const uint32_t sbase = smem_u32(sm);
    const int tid = threadIdx.x;
    const int wid = tid >> 5, lane = tid & 31;
    const int bn = blockIdx.x * 128;
    const int bm = blockIdx.y * 128;
    const int wm = (wid >> 2) * 32;
    const int wn = (wid & 3) * 32;

    wmma::fragment<wmma::accumulator, 16, 16, 16, float> facc[2][2];
    #pragma unroll
    for (int i = 0; i < 2; i++)
        #pragma unroll
        for (int j = 0; j < 2; j++) wmma::fill_fragment(facc[i][j], 0.0f);

    auto stage = [&](int t, int buf) {
        const int kk = t * 64;
        const uint32_t b0 = sbase + (uint32_t)buf * 36864u;
        #pragma unroll
        for (int s = 0; s < 2; s++) {
            int id = tid + s * 512;          // 1024 16B-chunks per array
            int row = id >> 3, c8 = id & 7;
            uint32_t so = (uint32_t)(row * 144 + c8 * 16);
            size_t ga = (size_t)(bm + row) * K + kk + c8 * 8;
            size_t gb = (size_t)(bn + row) * K + kk + c8 * 8;
            CP_ASYNC16(b0 +         so, A_g + ga);
            CP_ASYNC16(b0 + 18432 + so, B_g + gb);
        }
        CP_COMMIT();
    };

    stage(0, 0);
    if (T > 1) stage(1, 1);
    for (int t = 0; t < T; t++) {
        if (t == T - 1) { CP_WAIT0(); } else { CP_WAIT1(); }
        __syncthreads();
        if (t + 2 < T) stage(t + 2, (t + 2) % 3);

        const __half* As = sm + (size_t)(t % 3) * 18432;   // 36864B / 2
        const __half* Bs = As + 9216;

        #pragma unroll
        for (int ks = 0; ks < 4; ks++) {
            const int k0 = ks * 16;
            wmma::fragment<wmma::matrix_a, 16, 16, 16, __half, wmma::row_major> fa[2];
            wmma::fragment<wmma::matrix_b, 16, 16, 16, __half, wmma::col_major> fb[2];
            #pragma unroll
            for (int i = 0; i < 2; i++)
                wmma::load_matrix_sync(fa[i], As + (wm + i*16) * LDT + k0, LDT);
            #pragma unroll
            for (int j = 0; j < 2; j++)
                wmma::load_matrix_sync(fb[j], Bs + (wn + j*16) * LDT + k0, LDT);
            #pragma unroll
            for (int i = 0; i < 2; i++)
                #pragma unroll
                for (int j = 0; j < 2; j++)
                    wmma::mma_sync(facc[i][j], fa[i], fb[j], facc[i][j]);
        }
        __syncthreads();
    }

    // ----- epilogue -----
    float* tile = (float*)sm + wid * (32 * 36);
    #pragma unroll
    for (int i = 0; i < 2; i++)
        #pragma unroll
        for (int j = 0; j < 2; j++)
            wmma::store_matrix_sync(tile + (i*16) * 36 + j*16, facc[i][j], 36, wmma::mem_row_major);
    __syncwarp();

    const int c = bn + wn + lane;
    const float bv = bias[c];
    if (MODE == 0) {
        const int which = c >> 10, rem = c & 1023;
        const int hh = rem >> 6, p = rem & 63;
        __half* dst = (which == 0) ? g_qh : (which == 1) ? g_kh : g_vh;
        #pragma unroll 4
        for (int i = 0; i < 32; i++) {
            int m = bm + wm + i, bb = m >> 10, tok = m & 1023;
            dst[((size_t)(bb*H_ + hh) * N_ + tok) * P_ + p] = __float2half_rn(tile[i*36 + lane] + bv);
        }
    } else if (MODE == 1) {
        #pragma unroll 4
        for (int i = 0; i < 32; i++) {
            int m = bm + wm + i;
            float v = gelu_f(tile[i*36 + lane] + bv);
            g_h1[(size_t)m * DFF_ + c] = __float2half_rn(v);
        }
    } else {
        #pragma unroll 4
        for (int i = 0; i < 32; i++) {
            int m = bm + wm + i;
            size_t o = (size_t)m * D_ + c;
            Cout[o] = tile[i*36 + lane] + bv + g_s1[o];
        }
    }
}

// ---------------- WMMA flash attention (unchanged from round 12, passing) ----------
#define AT_LD 72
#define ATTN_SMEM 130048

__global__ void __launch_bounds__(256) attn_kernel(const float* __restrict__ prior,
                                                   const float* __restrict__ alpha_p,
                                                   const float* __restrict__ x)
{
    extern __shared__ char smc[];
    __half* Qs = (__half*)smc;                   // 128 x 72 fp16
    __half* Ks = (__half*)(smc + 18432);         // 64  x 72 fp16 (row j, cols p)
    __half* Vt = (__half*)(smc + 27648);         // 64  x 72 fp16 (row p, cols j)
    float*  Ss = (float*) (smc + 36864);         // 128 x 72 fp32
    __half* Ps = (__half*)(smc + 73728);         // 128 x 72 fp16
    float*  Os = (float*) (smc + 92160);         // 128 x 72 fp32
    float*  mrow = (float*)(smc + 129024);       // 128
    float*  lrow = (float*)(smc + 129536);       // 128

    const int tid = threadIdx.x;
    const int wid = tid >> 5;
    const int bh = blockIdx.x, b = bh >> 4, h = bh & 15;
    const int qt = blockIdx.y;
    const float alpha = alpha_p[0];

    const __half* Qg = g_qh + ((size_t)bh * N_ + qt * 128) * P_;
    for (int i = tid; i < 1024; i += 256) {
        int r = i >> 3, c8 = i & 7;
        *(uint4*)(Qs + r * AT_LD + c8 * 8) = *(const uint4*)(Qg + r * 64 + c8 * 8);
    }
    for (int i = tid; i < 128; i += 256) { mrow[i] = -1e30f; lrow[i] = 0.f; }
    for (int i = tid; i < 8192; i += 256) {
        int r = i >> 6, c = i & 63;
        Os[r * AT_LD + c] = 0.f;
    }

    const int r_s = tid >> 1, c0 = (tid & 1) * 32;
    const int qrow = qt * 128 + r_s;
    const float* prow = prior + ((size_t)b * N_ + qrow) * N_;

    for (int kt = 0; kt < 16; kt++) {
        __syncthreads();
        const __half* Kg = g_kh + ((size_t)bh * N_ + kt * 64) * P_;
        const __half* Vg = g_vh + ((size_t)bh * N_ + kt * 64) * P_;
        for (int i = tid; i < 512; i += 256) {
            int r = i >> 3, c8 = i & 7;
            *(uint4*)(Ks + r * AT_LD + c8 * 8) = *(const uint4*)(Kg + r * 64 + c8 * 8);
        }
        for (int i = tid; i < 4096; i += 256) {
            int j = i >> 6, p = i & 63;
            Vt[p * AT_LD + j] = Vg[j * 64 + p];
        }
        float4 pr[8];
        #pragma unroll
        for (int i = 0; i < 8; i++)
            pr[i] = *(const float4*)(prow + kt * 64 + c0 + i * 4);
        __syncthreads();

        // ---- S = Q K^T (warp: 16 x 64) ----
        {
            wmma::fragment<wmma::accumulator, 16, 16, 16, float> sacc[4];
            #pragma unroll
            for (int nf = 0; nf < 4; nf++) wmma::fill_fragment(sacc[nf], 0.0f);
            #pragma unroll
            for (int ks = 0; ks < 4; ks++) {
                wmma::fragment<wmma::matrix_a, 16, 16, 16, __half, wmma::row_major> fa;
                wmma::load_matrix_sync(fa, Qs + (wid * 16) * AT_LD + ks * 16, AT_LD);
                #pragma unroll
                for (int nf = 0; nf < 4; nf++) {
                    wmma::fragment<wmma::matrix_b, 16, 16, 16, __half, wmma::col_major> fb;
                    wmma::load_matrix_sync(fb, Ks + (nf * 16) * AT_LD + ks * 16, AT_LD);
                    wmma::mma_sync(sacc[nf], fa, fb, sacc[nf]);
                }
            }
            #pragma unroll
            for (int nf = 0; nf < 4; nf++)
                wmma::store_matrix_sync(Ss + (wid * 16) * AT_LD + nf * 16, sacc[nf],
                                        AT_LD, wmma::mem_row_major);
        }
        __syncthreads();

        // ---- softmax ----
        {
            float sv[32];
            float mx = -1e30f;
            #pragma unroll
            for (int i = 0; i < 32; i++) {
                float v = Ss[r_s * AT_LD + c0 + i];
                float pv = (&pr[i >> 2].x)[i & 3];
                v = (v + alpha * pv) * FACTOR_;
                sv[i] = v;
                mx = fmaxf(mx, v);
            }
            mx = fmaxf(mx, __shfl_xor_sync(0xffffffffu, mx, 1));
            float mold = mrow[r_s];
            float mnew = fmaxf(mold, mx);
            float rsum = 0.f;
            #pragma unroll
            for (int i = 0; i < 16; i++) {
                float e0 = __expf(sv[2*i]   - mnew);
                float e1 = __expf(sv[2*i+1] - mnew);
                rsum += e0 + e1;
                *(__half2*)(Ps + r_s * AT_LD + c0 + 2*i) = __floats2half2_rn(e0, e1);
            }
            rsum += __shfl_xor_sync(0xffffffffu, rsum, 1);
            float sc = __expf(mold - mnew);
            if ((tid & 1) == 0) { mrow[r_s] = mnew; lrow[r_s] = lrow[r_s] * sc + rsum; }
            #pragma unroll
            for (int i = 0; i < 32; i++)
                Os[r_s * AT_LD + c0 + i] *= sc;
        }
        __syncthreads();

        // ---- O += P V ----
        {
            wmma::fragment<wmma::accumulator, 16, 16, 16, float> oacc[4];
            #pragma unroll
            for (int nf = 0; nf < 4; nf++)
                wmma::load_matrix_sync(oacc[nf], Os + (wid * 16) * AT_LD + nf * 16,
                                       AT_LD, wmma::mem_row_major);
            #pragma unroll
            for (int ks = 0; ks < 4; ks++) {
                wmma::fragment<wmma::matrix_a, 16, 16, 16, __half, wmma::row_major> fa;
                wmma::load_matrix_sync(fa, Ps + (wid * 16) * AT_LD + ks * 16, AT_LD);
                #pragma unroll
                for (int nf = 0; nf < 4; nf++) {
                    wmma::fragment<wmma::matrix_b, 16, 16, 16, __half, wmma::col_major> fb;
                    wmma::load_matrix_sync(fb, Vt + (nf * 16) * AT_LD + ks * 16, AT_LD);
                    wmma::mma_sync(oacc[nf], fa, fb, oacc[nf]);
                }
            }
            #pragma unroll
            for (int nf = 0; nf < 4; nf++)
                wmma::store_matrix_sync(Os + (wid * 16) * AT_LD + nf * 16, oacc[nf],
                                        AT_LD, wmma::mem_row_major);
        }
    }
    __syncthreads();

    // ---- s1 = x + O/l ----
    {
        float inv = 1.0f / lrow[r_s];
        size_t off = ((size_t)b * N_ + qrow) * D_ + h * P_ + c0;
        #pragma unroll
        for (int i = 0; i < 8; i++) {
            float4 xv = *(const float4*)(x + off + i * 4);
            float4 o;
            o.x = xv.x + Os[r_s * AT_LD + c0 + i*4 + 0] * inv;
            o.y = xv.y + Os[r_s * AT_LD + c0 + i*4 + 1] * inv;
            o.z = xv.z + Os[r_s * AT_LD + c0 + i*4 + 2] * inv;
            o.w = xv.w + Os[r_s * AT_LD + c0 + i*4 + 3] * inv;
            *(float4*)&g_s1[off + i * 4] = o;
        }
    }
}

// ---------------- launch ----------------
extern "C" void kernel_launch(void* const* d_in, const int* in_sizes, int n_in,
                              void* d_out, int out_size)
{
    const float* x     = (const float*)d_in[0];
    const float* prior = (const float*)d_in[1];
    const float* Wqkv  = (const float*)d_in[2];
    const float* bqkv  = (const float*)d_in[3];
    const float* alpha = (const float*)d_in[4];
    const float* ln1_g = (const float*)d_in[5];
    const float* ln1_b = (const float*)d_in[6];
    const float* ln2_g = (const float*)d_in[7];
    const float* ln2_b = (const float*)d_in[8];
    const float* w1    = (const float*)d_in[9];
    const float* b1    = (const float*)d_in[10];
    const float* w2    = (const float*)d_in[11];
    const float* b2    = (const float*)d_in[12];
    float* out = (float*)d_out;

    cudaFuncSetAttribute(attn_kernel, cudaFuncAttributeMaxDynamicSharedMemorySize, ATTN_SMEM);
    cudaFuncSetAttribute(wgemm<0>, cudaFuncAttributeMaxDynamicSharedMemorySize, GEMM_SMEM);
    cudaFuncSetAttribute(wgemm<1>, cudaFuncAttributeMaxDynamicSharedMemorySize, GEMM_SMEM);
    cudaFuncSetAttribute(wgemm<2>, cudaFuncAttributeMaxDynamicSharedMemorySize, GEMM_SMEM);

    // 0. weight transpose -> fp16
    trans_split<0><<<dim3(3072/32, 1024/32), 256>>>(Wqkv);
    trans_split<1><<<dim3(4096/32, 1024/32), 256>>>(w1);
    trans_split<2><<<dim3(1024/32, 4096/32), 256>>>(w2);

    // 1. z1 = LN1(x)  (fp16)
    ln_kernel<0><<<M_, 256>>>(x, ln1_g, ln1_b);
    // 2. qkv GEMM -> fp16 q/k/v head layout
    wgemm<0><<<dim3(3072/128, M_/128), 512, GEMM_SMEM>>>(bqkv, nullptr);
    // 3. WMMA flash attention + prior + residual -> s1 (fp32)
    attn_kernel<<<dim3(B_*H_, N_/128), 256, ATTN_SMEM>>>(prior, alpha, x);
    // 4. z2 = LN2(s1)  (fp16)
    ln_kernel<1><<<M_, 256>>>(x, ln2_g, ln2_b);
    // 5. h1 = gelu(z2 @ w1 + b1)  (fp16)
    wgemm<1><<<dim3(4096/128, M_/128), 512, GEMM_SMEM>>>(b1, nullptr);
    // 6. out = s1 + h1 @ w2 + b2  (fp32)
    wgemm<2><<<dim3(1024/128, M_/128), 512, GEMM_SMEM>>>(b2, out);
}

// round 15
// speedup vs baseline: 4.2256x; 1.1430x over previous
#include <cuda_runtime.h>
#include <cuda_fp16.h>
#include <mma.h>
#include <math.h>
#include <stdint.h>

using namespace nvcuda;

#define B_   8
#define N_   1024
#define D_   1024
#define H_   16
#define P_   64
#define DFF_ 4096
#define M_   (B_*N_)          // 8192 tokens
#define FACTOR_ 0.125f        // 1/sqrt(64)

// ---------------- scratch (static device arrays; no allocations) ----------------
__device__ float g_s1[M_*D_];

// fp16 q/k/v in head layout [bh][n][p]
__device__ __align__(128) __half g_qh[M_*D_];
__device__ __align__(128) __half g_kh[M_*D_];
__device__ __align__(128) __half g_vh[M_*D_];

// single-fp16 activations
__device__ __align__(128) __half g_z1[M_*D_];
__device__ __align__(128) __half g_z2[M_*D_];
__device__ __align__(128) __half g_h1[M_*DFF_];

// transposed single-fp16 weights: WT[n][k] = W[k][n]
__device__ __align__(128) __half g_wqkvT[3072*1024];
__device__ __align__(128) __half g_w1T [4096*1024];
__device__ __align__(128) __half g_w2T [1024*4096];

// ---------------- helpers ----------------
__device__ __forceinline__ uint32_t smem_u32(const void* p) {
    uint32_t a;
    asm("{ .reg .u64 t; cvta.to.shared.u64 t, %1; cvt.u32.u64 %0, t; }" : "=r"(a) : "l"(p));
    return a;
}
#define CP_ASYNC16(sa, gp) \
    asm volatile("cp.async.cg.shared.global [%0], [%1], 16;" :: "r"(sa), "l"(gp))
#define CP_COMMIT() asm volatile("cp.async.commit_group;" ::: "memory")
#define CP_WAIT1()  asm volatile("cp.async.wait_group 1;" ::: "memory")
#define CP_WAIT0()  asm volatile("cp.async.wait_group 0;" ::: "memory")

__device__ __forceinline__ float gelu_f(float x) {
    float u = 0.7978845608028654f * (x + 0.044715f * x * x * x);
    return 0.5f * x * (1.0f + tanhf(u));
}

// ---------------- layernorm -> single fp16 ----------------
template<int SRC>
__global__ void __launch_bounds__(256) ln_kernel(const float* __restrict__ xin,
                                                 const float* __restrict__ gamma,
                                                 const float* __restrict__ beta)
{
    const float* in = (SRC == 0) ? xin : g_s1;
    __half* outh = (SRC == 0) ? g_z1 : g_z2;
    int row = blockIdx.x;
    int tid = threadIdx.x;
    const float4* xr = (const float4*)(in + (size_t)row * D_);
    float4 v = xr[tid];
    float s  = v.x + v.y + v.z + v.w;
    float sq = v.x*v.x + v.y*v.y + v.z*v.z + v.w*v.w;
    #pragma unroll
    for (int off = 16; off; off >>= 1) {
        s  += __shfl_xor_sync(0xffffffffu, s,  off);
        sq += __shfl_xor_sync(0xffffffffu, sq, off);
    }
    __shared__ float red0[8], red1[8];
    int w = tid >> 5, l = tid & 31;
    if (l == 0) { red0[w] = s; red1[w] = sq; }
    __syncthreads();
    if (tid < 32) {
        s  = (tid < 8) ? red0[tid] : 0.f;
        sq = (tid < 8) ? red1[tid] : 0.f;
        #pragma unroll
        for (int off = 4; off; off >>= 1) {
            s  += __shfl_xor_sync(0xffffffffu, s,  off);
            sq += __shfl_xor_sync(0xffffffffu, sq, off);
        }
        if (tid == 0) { red0[0] = s; red1[0] = sq; }
    }
    __syncthreads();
    float mu  = red0[0] * (1.0f/1024.0f);
    float var = red1[0] * (1.0f/1024.0f) - mu * mu;
    float rs  = rsqrtf(var + 1e-5f);
    float4 g4 = ((const float4*)gamma)[tid];
    float4 b4 = ((const float4*)beta)[tid];
    float o[4];
    o[0] = (v.x - mu) * rs * g4.x + b4.x;
    o[1] = (v.y - mu) * rs * g4.y + b4.y;
    o[2] = (v.z - mu) * rs * g4.z + b4.z;
    o[3] = (v.w - mu) * rs * g4.w + b4.w;
    size_t base = (size_t)row * D_ + tid * 4;
    *(__half2*)(outh + base)     = __floats2half2_rn(o[0], o[1]);
    *(__half2*)(outh + base + 2) = __floats2half2_rn(o[2], o[3]);
}

// ---------------- weight transpose to single fp16: W[K][N] -> WT[n][k] ----------------
template<int WSEL>
__global__ void __launch_bounds__(256) trans_split(const float* __restrict__ W)
{
    constexpr int K = (WSEL == 2) ? 4096 : 1024;
    constexpr int N = (WSEL == 0) ? 3072 : (WSEL == 1) ? 4096 : 1024;
    __half* oh = (WSEL == 0) ? g_wqkvT : (WSEL == 1) ? g_w1T : g_w2T;
    __shared__ float t[32][33];
    int n0 = blockIdx.x * 32, k0 = blockIdx.y * 32;
    int lx = threadIdx.x & 31, ly = threadIdx.x >> 5;
    #pragma unroll
    for (int rr = 0; rr < 4; rr++)
        t[ly + rr*8][lx] = W[(size_t)(k0 + ly + rr*8) * N + n0 + lx];
    __syncthreads();
    #pragma unroll
    for (int rr = 0; rr < 4; rr++) {
        int n = n0 + ly + rr*8, k = k0 + lx;
        oh[(size_t)n * K + k] = __float2half_rn(t[lx][ly + rr*8]);
    }
}

// ---------------- WMMA fp16 GEMM: CTA 128x128, KC=64, 3-stage cp.async, 512 thr --------
// single sync per k-chunk (stage(t+2) targets the buffer last read at t-1, which all
// threads finished before the sync-after-wait at t), plus one sync before the epilogue.
#define GEMM_SMEM 110592
#define LDT 72

template<int MODE>
__global__ void __launch_bounds__(512) wgemm(const float* __restrict__ bias,
                                             float* __restrict__ Cout)
{
    constexpr int K = (MODE == 2) ? 4096 : 1024;
    constexpr int T = K / 64;
    const __half* A_g = (MODE == 0) ? g_z1 : (MODE == 1) ? g_z2 : g_h1;
    const __half* B_g = (MODE == 0) ? g_wqkvT : (MODE == 1) ? g_w1T : g_w2T;

    extern __shared__ __half sm[];
    const uint32_t sbase = smem_u32(sm);
    const int tid = threadIdx.x;
    const int wid = tid >> 5, lane = tid & 31;
    const int bn = blockIdx.x * 128;
    const int bm = blockIdx.y * 128;
    const int wm = (wid >> 2) * 32;
    const int wn = (wid & 3) * 32;

    wmma::fragment<wmma::accumulator, 16, 16, 16, float> facc[2][2];
    #pragma unroll
    for (int i = 0; i < 2; i++)
        #pragma unroll
        for (int j = 0; j < 2; j++) wmma::fill_fragment(facc[i][j], 0.0f);

    auto stage = [&](int t, int buf) {
        const int kk = t * 64;
        const uint32_t b0 = sbase + (uint32_t)buf * 36864u;
        #pragma unroll
        for (int s = 0; s < 2; s++) {
            int id = tid + s * 512;
            int row = id >> 3, c8 = id & 7;
            uint32_t so = (uint32_t)(row * 144 + c8 * 16);
            size_t ga = (size_t)(bm + row) * K + kk + c8 * 8;
            size_t gb = (size_t)(bn + row) * K + kk + c8 * 8;
            CP_ASYNC16(b0 +         so, A_g + ga);
            CP_ASYNC16(b0 + 18432 + so, B_g + gb);
        }
        CP_COMMIT();
    };

    stage(0, 0);
    if (T > 1) stage(1, 1);
    for (int t = 0; t < T; t++) {
        if (t == T - 1) { CP_WAIT0(); } else { CP_WAIT1(); }
        __syncthreads();
        if (t + 2 < T) stage(t + 2, (t + 2) % 3);

        const __half* As = sm + (size_t)(t % 3) * 18432;
        const __half* Bs = As + 9216;

        #pragma unroll
        for (int ks = 0; ks < 4; ks++) {
            const int k0 = ks * 16;
            wmma::fragment<wmma::matrix_a, 16, 16, 16, __half, wmma::row_major> fa[2];
            wmma::fragment<wmma::matrix_b, 16, 16, 16, __half, wmma::col_major> fb[2];
            #pragma unroll
            for (int i = 0; i < 2; i++)
                wmma::load_matrix_sync(fa[i], As + (wm + i*16) * LDT + k0, LDT);
            #pragma unroll
            for (int j = 0; j < 2; j++)
                wmma::load_matrix_sync(fb[j], Bs + (wn + j*16) * LDT + k0, LDT);
            #pragma unroll
            for (int i = 0; i < 2; i++)
                #pragma unroll
                for (int j = 0; j < 2; j++)
                    wmma::mma_sync(facc[i][j], fa[i], fb[j], facc[i][j]);
        }
    }
    __syncthreads();   // protect smem reuse by epilogue tiles

    // ----- epilogue -----
    float* tile = (float*)sm + wid * (32 * 36);
    #pragma unroll
    for (int i = 0; i < 2; i++)
        #pragma unroll
        for (int j = 0; j < 2; j++)
            wmma::store_matrix_sync(tile + (i*16) * 36 + j*16, facc[i][j], 36, wmma::mem_row_major);
    __syncwarp();

    const int c = bn + wn + lane;
    const float bv = bias[c];
    if (MODE == 0) {
        const int which = c >> 10, rem = c & 1023;
        const int hh = rem >> 6, p = rem & 63;
        __half* dst = (which == 0) ? g_qh : (which == 1) ? g_kh : g_vh;
        #pragma unroll 4
        for (int i = 0; i < 32; i++) {
            int m = bm + wm + i, bb = m >> 10, tok = m & 1023;
            dst[((size_t)(bb*H_ + hh) * N_ + tok) * P_ + p] = __float2half_rn(tile[i*36 + lane] + bv);
        }
    } else if (MODE == 1) {
        #pragma unroll 4
        for (int i = 0; i < 32; i++) {
            int m = bm + wm + i;
            float v = gelu_f(tile[i*36 + lane] + bv);
            g_h1[(size_t)m * DFF_ + c] = __float2half_rn(v);
        }
    } else {
        #pragma unroll 4
        for (int i = 0; i < 32; i++) {
            int m = bm + wm + i;
            size_t o = (size_t)m * D_ + c;
            Cout[o] = tile[i*36 + lane] + bv + g_s1[o];
        }
    }
}

// ---------------- WMMA flash attention: cp.async double-buffered K/V, row-major V ----
// smem bytes: Qs 0..18432 | buf0 K 18432 V 27648 | buf1 K 36864 V 46080 |
//             Ss 55296 (fp32 128x72) | Ps 92160 | Os 110592 (fp32) | m 147456 l 147968
#define AT_LD 72
#define ATTN_SMEM 148480

__global__ void __launch_bounds__(256) attn_kernel(const float* __restrict__ prior,
                                                   const float* __restrict__ alpha_p,
                                                   const float* __restrict__ x)
{
    extern __shared__ char smc[];
    __half* Qs = (__half*)smc;
    float*  Ss = (float*) (smc + 55296);
    __half* Ps = (__half*)(smc + 92160);
    float*  Os = (float*) (smc + 110592);
    float*  mrow = (float*)(smc + 147456);
    float*  lrow = (float*)(smc + 147968);

    const uint32_t sb = smem_u32(smc);
    const int tid = threadIdx.x;
    const int wid = tid >> 5;
    const int bh = blockIdx.x, b = bh >> 4, h = bh & 15;
    const int qt = blockIdx.y;
    const float alpha = alpha_p[0];

    // stage Q (128 x 64 fp16)
    const __half* Qg = g_qh + ((size_t)bh * N_ + qt * 128) * P_;
    for (int i = tid; i < 1024; i += 256) {
        int r = i >> 3, c8 = i & 7;
        *(uint4*)(Qs + r * AT_LD + c8 * 8) = *(const uint4*)(Qg + r * 64 + c8 * 8);
    }
    for (int i = tid; i < 128; i += 256) { mrow[i] = -1e30f; lrow[i] = 0.f; }
    for (int i = tid; i < 8192; i += 256) {
        int r = i >> 6, c = i & 63;
        Os[r * AT_LD + c] = 0.f;
    }

    const int r_s = tid >> 1, c0 = (tid & 1) * 32;
    const int qrow = qt * 128 + r_s;
    const float* prow = prior + ((size_t)b * N_ + qrow) * N_;

    auto stageKV = [&](int kt, int buf) {
        const __half* Kg = g_kh + ((size_t)bh * N_ + kt * 64) * P_;
        const __half* Vg = g_vh + ((size_t)bh * N_ + kt * 64) * P_;
        const uint32_t kb = sb + 18432u + (uint32_t)buf * 18432u;
        const uint32_t vb = kb + 9216u;
        const int r = tid >> 3, c8 = tid & 7;
        #pragma unroll
        for (int s = 0; s < 2; s++) {
            int row = r + s * 32;
            uint32_t so = (uint32_t)(row * 144 + c8 * 16);
            CP_ASYNC16(kb + so, Kg + row * 64 + c8 * 8);
            CP_ASYNC16(vb + so, Vg + row * 64 + c8 * 8);
        }
        CP_COMMIT();
    };

    stageKV(0, 0);

    for (int kt = 0; kt < 16; kt++) {
        // prior prefetch for this iteration (LDGs ride across the syncs below)
        float4 pr[8];
        #pragma unroll
        for (int i = 0; i < 8; i++)
            pr[i] = *(const float4*)(prow + kt * 64 + c0 + i * 4);

        __syncthreads();   // PV of kt-1 done -> safe to overwrite buf (kt+1)&1
        if (kt + 1 < 16) { stageKV(kt + 1, (kt + 1) & 1); CP_WAIT1(); }
        else             { CP_WAIT0(); }
        __syncthreads();   // K/V of kt visible to all threads

        const __half* Ks = (__half*)(smc + 18432 + (kt & 1) * 18432);
        const __half* Vs = Ks + 4608;   // +9216 bytes

        // ---- S = Q K^T (warp: 16 x 64) ----
        {
            wmma::fragment<wmma::accumulator, 16, 16, 16, float> sacc[4];
            #pragma unroll
            for (int nf = 0; nf < 4; nf++) wmma::fill_fragment(sacc[nf], 0.0f);
            #pragma unroll
            for (int ks = 0; ks < 4; ks++) {
                wmma::fragment<wmma::matrix_a, 16, 16, 16, __half, wmma::row_major> fa;
                wmma::load_matrix_sync(fa, Qs + (wid * 16) * AT_LD + ks * 16, AT_LD);
                #pragma unroll
                for (int nf = 0; nf < 4; nf++) {
                    wmma::fragment<wmma::matrix_b, 16, 16, 16, __half, wmma::col_major> fb;
                    wmma::load_matrix_sync(fb, Ks + (nf * 16) * AT_LD + ks * 16, AT_LD);
                    wmma::mma_sync(sacc[nf], fa, fb, sacc[nf]);
                }
            }
            #pragma unroll
            for (int nf = 0; nf < 4; nf++)
                wmma::store_matrix_sync(Ss + (wid * 16) * AT_LD + nf * 16, sacc[nf],
                                        AT_LD, wmma::mem_row_major);
        }
        __syncthreads();

        // ---- softmax (thread: row r_s, 32 cols; pair-reduce via shfl xor 1) ----
        {
            float sv[32];
            float mx = -1e30f;
            #pragma unroll
            for (int i = 0; i < 32; i++) {
                float v = Ss[r_s * AT_LD + c0 + i];
                float pv = (&pr[i >> 2].x)[i & 3];
                v = (v + alpha * pv) * FACTOR_;
                sv[i] = v;
                mx = fmaxf(mx, v);
            }
            mx = fmaxf(mx, __shfl_xor_sync(0xffffffffu, mx, 1));
            float mold = mrow[r_s];
            float mnew = fmaxf(mold, mx);
            float rsum = 0.f;
            #pragma unroll
            for (int i = 0; i < 16; i++) {
                float e0 = __expf(sv[2*i]   - mnew);
                float e1 = __expf(sv[2*i+1] - mnew);
                rsum += e0 + e1;
                *(__half2*)(Ps + r_s * AT_LD + c0 + 2*i) = __floats2half2_rn(e0, e1);
            }
            rsum += __shfl_xor_sync(0xffffffffu, rsum, 1);
            float sc = __expf(mold - mnew);
            if ((tid & 1) == 0) { mrow[r_s] = mnew; lrow[r_s] = lrow[r_s] * sc + rsum; }
            #pragma unroll
            for (int i = 0; i < 32; i++)
                Os[r_s * AT_LD + c0 + i] *= sc;
        }
        __syncthreads();

        // ---- O += P V (V row-major IS matrix_b row-major; no transpose) ----
        {
            wmma::fragment<wmma::accumulator, 16, 16, 16, float> oacc[4];
            #pragma unroll
            for (int nf = 0; nf < 4; nf++)
                wmma::load_matrix_sync(oacc[nf], Os + (wid * 16) * AT_LD + nf * 16,
                                       AT_LD, wmma::mem_row_major);
            #pragma unroll
            for (int ks = 0; ks < 4; ks++) {
                wmma::fragment<wmma::matrix_a, 16, 16, 16, __half, wmma::row_major> fa;
                wmma::load_matrix_sync(fa, Ps + (wid * 16) * AT_LD + ks * 16, AT_LD);
                #pragma unroll
                for (int nf = 0; nf < 4; nf++) {
                    wmma::fragment<wmma::matrix_b, 16, 16, 16, __half, wmma::row_major> fb;
                    wmma::load_matrix_sync(fb, Vs + (ks * 16) * AT_LD + nf * 16, AT_LD);
                    wmma::mma_sync(oacc[nf], fa, fb, oacc[nf]);
                }
            }
            #pragma unroll
            for (int nf = 0; nf < 4; nf++)
                wmma::store_matrix_sync(Os + (wid * 16) * AT_LD + nf * 16, oacc[nf],
                                        AT_LD, wmma::mem_row_major);
        }
    }
    __syncthreads();

    // ---- s1 = x + O/l ----
    {
        float inv = 1.0f / lrow[r_s];
        size_t off = ((size_t)b * N_ + qrow) * D_ + h * P_ + c0;
        #pragma unroll
        for (int i = 0; i < 8; i++) {
            float4 xv = *(const float4*)(x + off + i * 4);
            float4 o;
            o.x = xv.x + Os[r_s * AT_LD + c0 + i*4 + 0] * inv;
            o.y = xv.y + Os[r_s * AT_LD + c0 + i*4 + 1] * inv;
            o.z = xv.z + Os[r_s * AT_LD + c0 + i*4 + 2] * inv;
            o.w = xv.w + Os[r_s * AT_LD + c0 + i*4 + 3] * inv;
            *(float4*)&g_s1[off + i * 4] = o;
        }
    }
}

// ---------------- launch ----------------
extern "C" void kernel_launch(void* const* d_in, const int* in_sizes, int n_in,
                              void* d_out, int out_size)
{
    const float* x     = (const float*)d_in[0];
    const float* prior = (const float*)d_in[1];
    const float* Wqkv  = (const float*)d_in[2];
    const float* bqkv  = (const float*)d_in[3];
    const float* alpha = (const float*)d_in[4];
    const float* ln1_g = (const float*)d_in[5];
    const float* ln1_b = (const float*)d_in[6];
    const float* ln2_g = (const float*)d_in[7];
    const float* ln2_b = (const float*)d_in[8];
    const float* w1    = (const float*)d_in[9];
    const float* b1    = (const float*)d_in[10];
    const float* w2    = (const float*)d_in[11];
    const float* b2    = (const float*)d_in[12];
    float* out = (float*)d_out;

    cudaFuncSetAttribute(attn_kernel, cudaFuncAttributeMaxDynamicSharedMemorySize, ATTN_SMEM);
    cudaFuncSetAttribute(wgemm<0>, cudaFuncAttributeMaxDynamicSharedMemorySize, GEMM_SMEM);
    cudaFuncSetAttribute(wgemm<1>, cudaFuncAttributeMaxDynamicSharedMemorySize, GEMM_SMEM);
    cudaFuncSetAttribute(wgemm<2>, cudaFuncAttributeMaxDynamicSharedMemorySize, GEMM_SMEM);

    // 0. weight transpose -> fp16
    trans_split<0><<<dim3(3072/32, 1024/32), 256>>>(Wqkv);
    trans_split<1><<<dim3(4096/32, 1024/32), 256>>>(w1);
    trans_split<2><<<dim3(1024/32, 4096/32), 256>>>(w2);

    // 1. z1 = LN1(x)  (fp16)
    ln_kernel<0><<<M_, 256>>>(x, ln1_g, ln1_b);
    // 2. qkv GEMM -> fp16 q/k/v head layout
    wgemm<0><<<dim3(3072/128, M_/128), 512, GEMM_SMEM>>>(bqkv, nullptr);
    // 3. WMMA flash attention + prior + residual -> s1 (fp32)
    attn_kernel<<<dim3(B_*H_, N_/128), 256, ATTN_SMEM>>>(prior, alpha, x);
    // 4. z2 = LN2(s1)  (fp16)
    ln_kernel<1><<<M_, 256>>>(x, ln2_g, ln2_b);
    // 5. h1 = gelu(z2 @ w1 + b1)  (fp16)
    wgemm<1><<<dim3(4096/128, M_/128), 512, GEMM_SMEM>>>(b1, nullptr);
    // 6. out = s1 + h1 @ w2 + b2  (fp32)
    wgemm<2><<<dim3(1024/128, M_/128), 512, GEMM_SMEM>>>(b2, out);
}